// round 2
// baseline (speedup 1.0000x reference)
#include <cuda_runtime.h>
#include <math.h>

#define LQ 8192
#define LK 8192
#define DIM 128
#define KCHUNKS 8
#define SCALE 0.08838834764831845f  // 1/sqrt(128)

// scratch (no allocations allowed -> device globals)
__device__ float g_m[LQ];
__device__ float g_l[LQ];
__device__ float g_opart[(size_t)KCHUNKS * LQ * DIM];

// ---------------------------------------------------------------------------
// Kernel A: S = Q @ K^T * scale, written to att region.
// 128x128 block tile, 256 threads, 8x8 micro-tile with 16-strided ownership
// (conflict-free LDS in the main loop). Smem holds d-major (transposed) tiles.
// ---------------------------------------------------------------------------
__global__ __launch_bounds__(256) void qk_kernel(const float* __restrict__ Q,
                                                 const float* __restrict__ K,
                                                 float* __restrict__ S) {
    extern __shared__ float sm[];
    float* Qs = sm;               // [128 d][129] -> Qs[d*129 + m]
    float* Ks = sm + 128 * 129;   // [128 d][129] -> Ks[d*129 + n]

    const int tid = threadIdx.x;
    const int m0 = blockIdx.y * 128;
    const int n0 = blockIdx.x * 128;

    // load + transpose tiles into smem (one-time; 4-way store conflicts OK)
#pragma unroll
    for (int i = 0; i < 16; i++) {
        int f4 = i * 256 + tid;      // 0..4095
        int row = f4 >> 5;           // 0..127
        int c4 = f4 & 31;            // 0..31
        float4 q = *(const float4*)(Q + (size_t)(m0 + row) * DIM + c4 * 4);
        float4 k = *(const float4*)(K + (size_t)(n0 + row) * DIM + c4 * 4);
        Qs[(c4 * 4 + 0) * 129 + row] = q.x;
        Qs[(c4 * 4 + 1) * 129 + row] = q.y;
        Qs[(c4 * 4 + 2) * 129 + row] = q.z;
        Qs[(c4 * 4 + 3) * 129 + row] = q.w;
        Ks[(c4 * 4 + 0) * 129 + row] = k.x;
        Ks[(c4 * 4 + 1) * 129 + row] = k.y;
        Ks[(c4 * 4 + 2) * 129 + row] = k.z;
        Ks[(c4 * 4 + 3) * 129 + row] = k.w;
    }
    __syncthreads();

    const int tr = tid >> 4;   // 0..15 row group
    const int tc = tid & 15;   // 0..15 col group
    float acc[8][8];
#pragma unroll
    for (int i = 0; i < 8; i++)
#pragma unroll
        for (int j = 0; j < 8; j++) acc[i][j] = 0.f;

#pragma unroll 4
    for (int kk = 0; kk < DIM; kk++) {
        float a[8], b[8];
#pragma unroll
        for (int i = 0; i < 8; i++) a[i] = Qs[kk * 129 + tr + 16 * i];
#pragma unroll
        for (int j = 0; j < 8; j++) b[j] = Ks[kk * 129 + tc + 16 * j];
#pragma unroll
        for (int i = 0; i < 8; i++)
#pragma unroll
            for (int j = 0; j < 8; j++) acc[i][j] += a[i] * b[j];
    }

#pragma unroll
    for (int i = 0; i < 8; i++) {
        size_t rbase = (size_t)(m0 + tr + 16 * i) * LK + n0;
#pragma unroll
        for (int j = 0; j < 8; j++) {
            S[rbase + tc + 16 * j] = acc[i][j] * SCALE;
        }
    }
}

// ---------------------------------------------------------------------------
// Kernel B: per-row max and sum(exp(s - max)). One block per query row.
// Row data kept in registers (32 floats/thread), reduced via smem.
// ---------------------------------------------------------------------------
__global__ __launch_bounds__(256) void stats_kernel(const float* __restrict__ S) {
    __shared__ float red[256];
    const int tid = threadIdx.x;
    const size_t row = blockIdx.x;
    const float4* src = (const float4*)(S + row * LK);

    float4 v[8];
    float lm = -1e30f;
#pragma unroll
    for (int i = 0; i < 8; i++) {
        v[i] = src[i * 256 + tid];
        lm = fmaxf(lm, fmaxf(fmaxf(v[i].x, v[i].y), fmaxf(v[i].z, v[i].w)));
    }
    red[tid] = lm;
    __syncthreads();
    for (int s = 128; s > 0; s >>= 1) {
        if (tid < s) red[tid] = fmaxf(red[tid], red[tid + s]);
        __syncthreads();
    }
    const float m = red[0];
    __syncthreads();

    float ls = 0.f;
#pragma unroll
    for (int i = 0; i < 8; i++) {
        ls += __expf(v[i].x - m) + __expf(v[i].y - m) +
              __expf(v[i].z - m) + __expf(v[i].w - m);
    }
    red[tid] = ls;
    __syncthreads();
    for (int s = 128; s > 0; s >>= 1) {
        if (tid < s) red[tid] += red[tid + s];
        __syncthreads();
    }
    if (tid == 0) {
        g_m[row] = m;
        g_l[row] = red[0];
    }
}

// ---------------------------------------------------------------------------
// Kernel C: att = exp(S - m) / l  (in-place over the S values), fused with
// partial O += att @ V. Grid (KCHUNKS, LQ/128); each block owns a 128-row
// q-tile and a 1024-wide k-chunk; partial O goes to g_opart (deterministic).
// ---------------------------------------------------------------------------
__global__ __launch_bounds__(256) void softmax_pv_kernel(const float* __restrict__ V,
                                                         float* __restrict__ att) {
    extern __shared__ float sm[];
    float* Ps = sm;                 // [64 k][129] -> Ps[k*129 + qrow]
    float* Vs = sm + 64 * 129;      // [64 k][128] -> Vs[k*128 + dcol]
    float* mrow = Vs + 64 * 128;    // [128]
    float* ilrow = mrow + 128;      // [128]

    const int tid = threadIdx.x;
    const int q0 = blockIdx.y * 128;
    const int kstart = blockIdx.x * (LK / KCHUNKS);

    if (tid < 128) {
        mrow[tid] = g_m[q0 + tid];
        ilrow[tid] = 1.0f / g_l[q0 + tid];
    }
    __syncthreads();

    const int tr = tid >> 4;
    const int tc = tid & 15;
    float acc[8][8];
#pragma unroll
    for (int i = 0; i < 8; i++)
#pragma unroll
        for (int j = 0; j < 8; j++) acc[i][j] = 0.f;

    for (int t = 0; t < (LK / KCHUNKS) / 64; t++) {
        const int kb = kstart + t * 64;

        // load V tile [64][128]
#pragma unroll
        for (int i = 0; i < 8; i++) {
            int f4 = i * 256 + tid;
            int row = f4 >> 5;
            int c4 = f4 & 31;
            *(float4*)(Vs + row * 128 + c4 * 4) =
                *(const float4*)(V + (size_t)(kb + row) * DIM + c4 * 4);
        }

        // S tile [128 q][64 k]: read, softmax-normalize, write back, stage
        // transposed into Ps
#pragma unroll
        for (int i = 0; i < 8; i++) {
            int f4 = i * 256 + tid;
            int row = f4 >> 4;   // q row 0..127
            int c4 = f4 & 15;    // k group 0..15
            float* gp = att + (size_t)(q0 + row) * LK + kb + c4 * 4;
            float4 s = *(const float4*)gp;
            const float m = mrow[row];
            const float il = ilrow[row];
            float4 p;
            p.x = __expf(s.x - m) * il;
            p.y = __expf(s.y - m) * il;
            p.z = __expf(s.z - m) * il;
            p.w = __expf(s.w - m) * il;
            *(float4*)gp = p;
            Ps[(c4 * 4 + 0) * 129 + row] = p.x;
            Ps[(c4 * 4 + 1) * 129 + row] = p.y;
            Ps[(c4 * 4 + 2) * 129 + row] = p.z;
            Ps[(c4 * 4 + 3) * 129 + row] = p.w;
        }
        __syncthreads();

        // O += P @ V over this 64-wide k tile
#pragma unroll 2
        for (int kk = 0; kk < 64; kk++) {
            float a[8], b[8];
#pragma unroll
            for (int i = 0; i < 8; i++) a[i] = Ps[kk * 129 + tr + 16 * i];
#pragma unroll
            for (int j = 0; j < 8; j++) b[j] = Vs[kk * 128 + tc + 16 * j];
#pragma unroll
            for (int i = 0; i < 8; i++)
#pragma unroll
                for (int j = 0; j < 8; j++) acc[i][j] += a[i] * b[j];
        }
        __syncthreads();
    }

    float* op = g_opart + (size_t)blockIdx.x * ((size_t)LQ * DIM);
#pragma unroll
    for (int i = 0; i < 8; i++) {
        size_t rbase = (size_t)(q0 + tr + 16 * i) * DIM;
#pragma unroll
        for (int j = 0; j < 8; j++) {
            op[rbase + tc + 16 * j] = acc[i][j];
        }
    }
}

// ---------------------------------------------------------------------------
// Kernel D: reduce KCHUNKS partials into out.
// ---------------------------------------------------------------------------
__global__ __launch_bounds__(256) void reduce_kernel(float* __restrict__ out) {
    const size_t i = (size_t)blockIdx.x * 256 + threadIdx.x;
    float s = 0.f;
#pragma unroll
    for (int c = 0; c < KCHUNKS; c++) s += g_opart[(size_t)c * LQ * DIM + i];
    out[i] = s;
}

// ---------------------------------------------------------------------------
extern "C" void kernel_launch(void* const* d_in, const int* in_sizes, int n_in,
                              void* d_out, int out_size) {
    const float* Q = (const float*)d_in[0];
    const float* K = (const float*)d_in[1];
    const float* V = (const float*)d_in[2];
    float* out = (float*)d_out;                    // [LQ, DIM]
    float* att = out + (size_t)LQ * DIM;           // [LQ, LK]

    const int smemA = 2 * 128 * 129 * sizeof(float);                    // 132096
    const int smemC = (64 * 129 + 64 * 128 + 256) * sizeof(float);      // 66816
    cudaFuncSetAttribute(qk_kernel, cudaFuncAttributeMaxDynamicSharedMemorySize, smemA);
    cudaFuncSetAttribute(softmax_pv_kernel, cudaFuncAttributeMaxDynamicSharedMemorySize, smemC);

    qk_kernel<<<dim3(LK / 128, LQ / 128), 256, smemA>>>(Q, K, att);
    stats_kernel<<<LQ, 256>>>(att);
    softmax_pv_kernel<<<dim3(KCHUNKS, LQ / 128), 256, smemC>>>(V, att);
    reduce_kernel<<<(LQ * DIM) / 256, 256>>>(out);
}

// round 4
// speedup vs baseline: 1.4240x; 1.4240x over previous
#include <cuda_runtime.h>
#include <cuda_bf16.h>
#include <cstdint>
#include <math.h>

#define LQ 8192
#define LK 8192
#define DIM 128
#define KCH 16
#define SCALE 0.08838834764831845f  // 1/sqrt(128)

#define STRQ 136  // smem row stride (bf16 elems) for 128-wide tiles (272B)
#define STRP 72   // smem row stride (bf16 elems) for 64-wide tiles (144B)

// ---------------- device scratch (no allocations allowed) ----------------
__device__ __nv_bfloat16 g_qhi[(size_t)LQ * DIM], g_qlo[(size_t)LQ * DIM];
__device__ __nv_bfloat16 g_khi[(size_t)LK * DIM], g_klo[(size_t)LK * DIM];
__device__ __nv_bfloat16 g_vthi[(size_t)DIM * LK], g_vtlo[(size_t)DIM * LK];  // V^T [d][k]
__device__ float g_m[LQ], g_l[LQ];
__device__ float g_opart[(size_t)KCH * LQ * DIM];

// ---------------- helpers ----------------
__device__ __forceinline__ uint32_t smem_u32(const void* p) {
    uint32_t a;
    asm("{ .reg .u64 t; cvta.to.shared.u64 t, %1; cvt.u32.u64 %0, t; }" : "=r"(a) : "l"(p));
    return a;
}
__device__ __forceinline__ void ldsm4(uint32_t (&r)[4], uint32_t addr) {
    asm volatile("ldmatrix.sync.aligned.m8n8.x4.shared.b16 {%0,%1,%2,%3}, [%4];"
        : "=r"(r[0]), "=r"(r[1]), "=r"(r[2]), "=r"(r[3]) : "r"(addr));
}
__device__ __forceinline__ void mma16816(float (&c)[4], const uint32_t (&a)[4],
                                         uint32_t b0, uint32_t b1) {
    asm volatile("mma.sync.aligned.m16n8k16.row.col.f32.bf16.bf16.f32 "
        "{%0,%1,%2,%3}, {%4,%5,%6,%7}, {%8,%9}, {%0,%1,%2,%3};"
        : "+f"(c[0]), "+f"(c[1]), "+f"(c[2]), "+f"(c[3])
        : "r"(a[0]), "r"(a[1]), "r"(a[2]), "r"(a[3]), "r"(b0), "r"(b1));
}

// ---------------------------------------------------------------------------
// prep: fp32 -> bf16 hi/lo splits; Q prescaled; V transposed
// ---------------------------------------------------------------------------
__global__ __launch_bounds__(256) void prep_kernel(const float* __restrict__ Q,
                                                   const float* __restrict__ K,
                                                   const float* __restrict__ V) {
    size_t i = (size_t)blockIdx.x * 256 + threadIdx.x;
    float q = Q[i] * SCALE;
    __nv_bfloat16 qh = __float2bfloat16(q);
    g_qhi[i] = qh;
    g_qlo[i] = __float2bfloat16(q - __bfloat162float(qh));
    float k = K[i];
    __nv_bfloat16 kh = __float2bfloat16(k);
    g_khi[i] = kh;
    g_klo[i] = __float2bfloat16(k - __bfloat162float(kh));
    float v = V[i];
    __nv_bfloat16 vh = __float2bfloat16(v);
    __nv_bfloat16 vl = __float2bfloat16(v - __bfloat162float(vh));
    size_t kr = i >> 7;
    size_t d = i & 127;
    g_vthi[d * LK + kr] = vh;
    g_vtlo[d * LK + kr] = vl;
}

// ---------------------------------------------------------------------------
// Kernel A: S = Qs @ K^T via HMMA (scale folded into Q).
// 128x128 tile/CTA, 8 warps in 2x4 grid, each warp 64x32, 3-term hi/lo split.
// ---------------------------------------------------------------------------
__global__ __launch_bounds__(256) void qk_hmma_kernel(float* __restrict__ S) {
    extern __shared__ __align__(16) char smem[];
    __nv_bfloat16* Qhi = (__nv_bfloat16*)smem;        // [128][STRQ]
    __nv_bfloat16* Qlo = Qhi + 128 * STRQ;
    __nv_bfloat16* Khi = Qlo + 128 * STRQ;
    __nv_bfloat16* Klo = Khi + 128 * STRQ;

    const int tid = threadIdx.x, lane = tid & 31, wid = tid >> 5;
    const int m0 = blockIdx.y * 128, n0 = blockIdx.x * 128;

#pragma unroll
    for (int i = 0; i < 8; i++) {
        int idx = i * 256 + tid;
        int row = idx >> 4;
        int ch = (idx & 15) * 8;
        size_t gq = (size_t)(m0 + row) * DIM + ch;
        size_t gk = (size_t)(n0 + row) * DIM + ch;
        *(uint4*)(Qhi + row * STRQ + ch) = *(const uint4*)(g_qhi + gq);
        *(uint4*)(Qlo + row * STRQ + ch) = *(const uint4*)(g_qlo + gq);
        *(uint4*)(Khi + row * STRQ + ch) = *(const uint4*)(g_khi + gk);
        *(uint4*)(Klo + row * STRQ + ch) = *(const uint4*)(g_klo + gk);
    }
    __syncthreads();

    const int wm = (wid >> 2) * 64, wn = (wid & 3) * 32;
    float c[4][4][4];
#pragma unroll
    for (int mi = 0; mi < 4; mi++)
#pragma unroll
        for (int nj = 0; nj < 4; nj++)
#pragma unroll
            for (int e = 0; e < 4; e++) c[mi][nj][e] = 0.f;

    const uint32_t abase[3] = {smem_u32(Qhi), smem_u32(Qlo), smem_u32(Qhi)};
    const uint32_t bbase[3] = {smem_u32(Khi), smem_u32(Khi), smem_u32(Klo)};
    const int arow = lane & 15;
    const int acol = (lane >> 4) * 8;

#pragma unroll
    for (int s = 0; s < 3; s++) {
        const uint32_t ab = abase[s], bb = bbase[s];
#pragma unroll
        for (int k16 = 0; k16 < 8; k16++) {
            const int kc = k16 * 16 + acol;
            uint32_t a[4][4], b[2][4];
#pragma unroll
            for (int mi = 0; mi < 4; mi++)
                ldsm4(a[mi], ab + ((wm + mi * 16 + arow) * STRQ + kc) * 2);
#pragma unroll
            for (int nj = 0; nj < 2; nj++)
                ldsm4(b[nj], bb + ((wn + nj * 16 + arow) * STRQ + kc) * 2);
#pragma unroll
            for (int mi = 0; mi < 4; mi++)
#pragma unroll
                for (int n8 = 0; n8 < 4; n8++)
                    mma16816(c[mi][n8], a[mi], b[n8 >> 1][n8 & 1], b[n8 >> 1][(n8 & 1) + 2]);
        }
    }

    // store fp32 S
    const int r0 = lane >> 2, c0 = (lane & 3) * 2;
#pragma unroll
    for (int mi = 0; mi < 4; mi++) {
#pragma unroll
        for (int n8 = 0; n8 < 4; n8++) {
            size_t row = (size_t)(m0 + wm + mi * 16 + r0);
            size_t col = (size_t)(n0 + wn + n8 * 8 + c0);
            *(float2*)(S + row * LK + col) = make_float2(c[mi][n8][0], c[mi][n8][1]);
            *(float2*)(S + (row + 8) * LK + col) = make_float2(c[mi][n8][2], c[mi][n8][3]);
        }
    }
}

// ---------------------------------------------------------------------------
// Kernel B: per-row max and sum(exp(s - max))
// ---------------------------------------------------------------------------
__global__ __launch_bounds__(256) void stats_kernel(const float* __restrict__ S) {
    __shared__ float red[256];
    const int tid = threadIdx.x;
    const size_t row = blockIdx.x;
    const float4* src = (const float4*)(S + row * LK);

    float4 v[8];
    float lm = -1e30f;
#pragma unroll
    for (int i = 0; i < 8; i++) {
        v[i] = src[i * 256 + tid];
        lm = fmaxf(lm, fmaxf(fmaxf(v[i].x, v[i].y), fmaxf(v[i].z, v[i].w)));
    }
    red[tid] = lm;
    __syncthreads();
    for (int s = 128; s > 0; s >>= 1) {
        if (tid < s) red[tid] = fmaxf(red[tid], red[tid + s]);
        __syncthreads();
    }
    const float m = red[0];
    __syncthreads();

    float ls = 0.f;
#pragma unroll
    for (int i = 0; i < 8; i++) {
        ls += __expf(v[i].x - m) + __expf(v[i].y - m) +
              __expf(v[i].z - m) + __expf(v[i].w - m);
    }
    red[tid] = ls;
    __syncthreads();
    for (int s = 128; s > 0; s >>= 1) {
        if (tid < s) red[tid] += red[tid + s];
        __syncthreads();
    }
    if (tid == 0) {
        g_m[row] = m;
        g_l[row] = red[0];
    }
}

// ---------------------------------------------------------------------------
// Kernel C: att = exp(S-m)/l in place + partial O = P @ V via HMMA.
// grid (KCH, LQ/128); each CTA loops 8 k-tiles of 64, C frags in registers.
// ---------------------------------------------------------------------------
__global__ __launch_bounds__(256) void pv_hmma_kernel(float* __restrict__ att) {
    extern __shared__ __align__(16) char smem[];
    __nv_bfloat16* Phi = (__nv_bfloat16*)smem;        // [128][STRP]
    __nv_bfloat16* Plo = Phi + 128 * STRP;
    __nv_bfloat16* Vhi = Plo + 128 * STRP;
    __nv_bfloat16* Vlo = Vhi + 128 * STRP;
    float* sm_m = (float*)(Vlo + 128 * STRP);
    float* sm_il = sm_m + 128;

    const int tid = threadIdx.x, lane = tid & 31, wid = tid >> 5;
    const int q0 = blockIdx.y * 128;
    const int kcnk = blockIdx.x;

    if (tid < 128) {
        sm_m[tid] = g_m[q0 + tid];
        sm_il[tid] = 1.0f / g_l[q0 + tid];
    }
    __syncthreads();

    const int wm = (wid >> 2) * 64, wn = (wid & 3) * 32;
    float c[4][4][4];
#pragma unroll
    for (int mi = 0; mi < 4; mi++)
#pragma unroll
        for (int nj = 0; nj < 4; nj++)
#pragma unroll
            for (int e = 0; e < 4; e++) c[mi][nj][e] = 0.f;

    const uint32_t abase[3] = {smem_u32(Phi), smem_u32(Plo), smem_u32(Phi)};
    const uint32_t bbase[3] = {smem_u32(Vhi), smem_u32(Vhi), smem_u32(Vlo)};
    const int arow = lane & 15;
    const int acol = (lane >> 4) * 8;

    for (int t = 0; t < 8; t++) {
        const int kb = kcnk * (LK / KCH) + t * 64;

        // V^T tiles [d=128][64]
#pragma unroll
        for (int i = 0; i < 4; i++) {
            int idx = i * 256 + tid;
            int row = idx >> 3;
            int ch = (idx & 7) * 8;
            size_t go = (size_t)row * LK + kb + ch;
            *(uint4*)(Vhi + row * STRP + ch) = *(const uint4*)(g_vthi + go);
            *(uint4*)(Vlo + row * STRP + ch) = *(const uint4*)(g_vtlo + go);
        }

        // P tile: read S fp32 [128 q][64 k], normalize, write att, stage hi/lo
#pragma unroll
        for (int i = 0; i < 8; i++) {
            int idx = i * 256 + tid;
            int row = idx >> 4;
            int col = (idx & 15) * 4;
            float* gp = att + (size_t)(q0 + row) * LK + kb + col;
            float4 s = *(const float4*)gp;
            const float mm = sm_m[row];
            const float ii = sm_il[row];
            float e0 = __expf(s.x - mm) * ii;
            float e1 = __expf(s.y - mm) * ii;
            float e2 = __expf(s.z - mm) * ii;
            float e3 = __expf(s.w - mm) * ii;
            float4 p;
            p.x = e0; p.y = e1; p.z = e2; p.w = e3;
            *(float4*)gp = p;
            __nv_bfloat162 h01, h23, l01, l23;
            h01.x = __float2bfloat16(e0);
            h01.y = __float2bfloat16(e1);
            h23.x = __float2bfloat16(e2);
            h23.y = __float2bfloat16(e3);
            l01.x = __float2bfloat16(e0 - __bfloat162float(h01.x));
            l01.y = __float2bfloat16(e1 - __bfloat162float(h01.y));
            l23.x = __float2bfloat16(e2 - __bfloat162float(h23.x));
            l23.y = __float2bfloat16(e3 - __bfloat162float(h23.y));
            *(__nv_bfloat162*)(Phi + row * STRP + col) = h01;
            *(__nv_bfloat162*)(Phi + row * STRP + col + 2) = h23;
            *(__nv_bfloat162*)(Plo + row * STRP + col) = l01;
            *(__nv_bfloat162*)(Plo + row * STRP + col + 2) = l23;
        }
        __syncthreads();

#pragma unroll
        for (int s = 0; s < 3; s++) {
            const uint32_t ab = abase[s], bb = bbase[s];
#pragma unroll
            for (int k16 = 0; k16 < 4; k16++) {
                const int kc = k16 * 16 + acol;
                uint32_t a[4][4], b[2][4];
#pragma unroll
                for (int mi = 0; mi < 4; mi++)
                    ldsm4(a[mi], ab + ((wm + mi * 16 + arow) * STRP + kc) * 2);
#pragma unroll
                for (int nj = 0; nj < 2; nj++)
                    ldsm4(b[nj], bb + ((wn + nj * 16 + arow) * STRP + kc) * 2);
#pragma unroll
                for (int mi = 0; mi < 4; mi++)
#pragma unroll
                    for (int n8 = 0; n8 < 4; n8++)
                        mma16816(c[mi][n8], a[mi], b[n8 >> 1][n8 & 1], b[n8 >> 1][(n8 & 1) + 2]);
            }
        }
        __syncthreads();
    }

    float* op = g_opart + (size_t)kcnk * ((size_t)LQ * DIM);
    const int r0 = lane >> 2, c0 = (lane & 3) * 2;
#pragma unroll
    for (int mi = 0; mi < 4; mi++) {
#pragma unroll
        for (int n8 = 0; n8 < 4; n8++) {
            size_t row = (size_t)(q0 + wm + mi * 16 + r0);
            size_t col = (size_t)(wn + n8 * 8 + c0);
            *(float2*)(op + row * DIM + col) = make_float2(c[mi][n8][0], c[mi][n8][1]);
            *(float2*)(op + (row + 8) * DIM + col) = make_float2(c[mi][n8][2], c[mi][n8][3]);
        }
    }
}

// ---------------------------------------------------------------------------
// Kernel D: reduce KCH partials into out
// ---------------------------------------------------------------------------
__global__ __launch_bounds__(256) void reduce_kernel(float* __restrict__ out) {
    const size_t i = (size_t)blockIdx.x * 256 + threadIdx.x;
    float s = 0.f;
#pragma unroll
    for (int c = 0; c < KCH; c++) s += g_opart[(size_t)c * LQ * DIM + i];
    out[i] = s;
}

// ---------------------------------------------------------------------------
extern "C" void kernel_launch(void* const* d_in, const int* in_sizes, int n_in,
                              void* d_out, int out_size) {
    const float* Q = (const float*)d_in[0];
    const float* K = (const float*)d_in[1];
    const float* V = (const float*)d_in[2];
    float* out = (float*)d_out;             // [LQ, DIM]
    float* att = out + (size_t)LQ * DIM;    // [LQ, LK]

    const int smemA = 4 * 128 * STRQ * 2;              // 139264
    const int smemC = 4 * 128 * STRP * 2 + 2 * 512;    // 74752
    cudaFuncSetAttribute(qk_hmma_kernel, cudaFuncAttributeMaxDynamicSharedMemorySize, smemA);
    cudaFuncSetAttribute(pv_hmma_kernel, cudaFuncAttributeMaxDynamicSharedMemorySize, smemC);

    prep_kernel<<<(LQ * DIM) / 256, 256>>>(Q, K, V);
    qk_hmma_kernel<<<dim3(LK / 128, LQ / 128), 256, smemA>>>(att);
    stats_kernel<<<LQ, 256>>>(att);
    pv_hmma_kernel<<<dim3(KCH, LQ / 128), 256, smemC>>>(att);
    reduce_kernel<<<(LQ * DIM) / 256, 256>>>(out);
}

// round 5
// speedup vs baseline: 2.1494x; 1.5094x over previous
#include <cuda_runtime.h>
#include <cuda_bf16.h>
#include <cstdint>
#include <math.h>

#define LQ 8192
#define LK 8192
#define DIM 128
#define KCH 8
#define SCALE 0.08838834764831845f  // 1/sqrt(128)

#define STRQ 136  // smem row stride (bf16) for 128-wide tiles
#define STRP 72   // smem row stride (bf16) for 64-wide tiles (144B = 9*16B)

// ---------------- device scratch ----------------
__device__ __nv_bfloat16 g_qhi[(size_t)LQ * DIM], g_qlo[(size_t)LQ * DIM];
__device__ __nv_bfloat16 g_khi[(size_t)LK * DIM], g_klo[(size_t)LK * DIM];
__device__ __nv_bfloat16 g_vthi[(size_t)DIM * LK], g_vtlo[(size_t)DIM * LK];  // V^T [d][k]
__device__ float g_lpart[(size_t)LQ * 64];   // [row][64 n-blocks]
__device__ float g_il[LQ];
__device__ float g_opart[(size_t)KCH * LQ * DIM];

// ---------------- helpers ----------------
__device__ __forceinline__ uint32_t smem_u32(const void* p) {
    uint32_t a;
    asm("{ .reg .u64 t; cvta.to.shared.u64 t, %1; cvt.u32.u64 %0, t; }" : "=r"(a) : "l"(p));
    return a;
}
__device__ __forceinline__ void ldsm4(uint32_t (&r)[4], uint32_t addr) {
    asm volatile("ldmatrix.sync.aligned.m8n8.x4.shared.b16 {%0,%1,%2,%3}, [%4];"
        : "=r"(r[0]), "=r"(r[1]), "=r"(r[2]), "=r"(r[3]) : "r"(addr));
}
__device__ __forceinline__ void mma16816(float (&c)[4], const uint32_t (&a)[4],
                                         uint32_t b0, uint32_t b1) {
    asm volatile("mma.sync.aligned.m16n8k16.row.col.f32.bf16.bf16.f32 "
        "{%0,%1,%2,%3}, {%4,%5,%6,%7}, {%8,%9}, {%0,%1,%2,%3};"
        : "+f"(c[0]), "+f"(c[1]), "+f"(c[2]), "+f"(c[3])
        : "r"(a[0]), "r"(a[1]), "r"(a[2]), "r"(a[3]), "r"(b0), "r"(b1));
}
__device__ __forceinline__ void cpasync16(uint32_t dst, const void* src) {
    asm volatile("cp.async.cg.shared.global [%0], [%1], 16;" :: "r"(dst), "l"(src));
}
#define CP_COMMIT() asm volatile("cp.async.commit_group;" ::: "memory")
#define CP_WAIT(N)  asm volatile("cp.async.wait_group %0;" :: "n"(N) : "memory")

// ---------------------------------------------------------------------------
// prep: fp32 -> bf16 hi/lo splits; Q prescaled; V transposed
// ---------------------------------------------------------------------------
__global__ __launch_bounds__(256) void prep_kernel(const float* __restrict__ Q,
                                                   const float* __restrict__ K,
                                                   const float* __restrict__ V) {
    size_t i = (size_t)blockIdx.x * 256 + threadIdx.x;
    float q = Q[i] * SCALE;
    __nv_bfloat16 qh = __float2bfloat16(q);
    g_qhi[i] = qh;
    g_qlo[i] = __float2bfloat16(q - __bfloat162float(qh));
    float k = K[i];
    __nv_bfloat16 kh = __float2bfloat16(k);
    g_khi[i] = kh;
    g_klo[i] = __float2bfloat16(k - __bfloat162float(kh));
    float v = V[i];
    __nv_bfloat16 vh = __float2bfloat16(v);
    __nv_bfloat16 vl = __float2bfloat16(v - __bfloat162float(vh));
    size_t kr = i >> 7;
    size_t d = i & 127;
    g_vthi[d * LK + kr] = vh;
    g_vtlo[d * LK + kr] = vl;
}

// ---------------------------------------------------------------------------
// Kernel A: e = exp(Qs @ K^T) (unnormalized) + per-row partial sums.
// ---------------------------------------------------------------------------
__global__ __launch_bounds__(256) void qk_hmma_kernel(float* __restrict__ att) {
    extern __shared__ __align__(16) char smem[];
    __nv_bfloat16* Qhi = (__nv_bfloat16*)smem;        // [128][STRQ]
    __nv_bfloat16* Qlo = Qhi + 128 * STRQ;
    __nv_bfloat16* Khi = Qlo + 128 * STRQ;
    __nv_bfloat16* Klo = Khi + 128 * STRQ;

    const int tid = threadIdx.x, lane = tid & 31, wid = tid >> 5;
    const int m0 = blockIdx.y * 128, n0 = blockIdx.x * 128;

#pragma unroll
    for (int i = 0; i < 8; i++) {
        int idx = i * 256 + tid;
        int row = idx >> 4;
        int ch = (idx & 15) * 8;
        size_t gq = (size_t)(m0 + row) * DIM + ch;
        size_t gk = (size_t)(n0 + row) * DIM + ch;
        *(uint4*)(Qhi + row * STRQ + ch) = *(const uint4*)(g_qhi + gq);
        *(uint4*)(Qlo + row * STRQ + ch) = *(const uint4*)(g_qlo + gq);
        *(uint4*)(Khi + row * STRQ + ch) = *(const uint4*)(g_khi + gk);
        *(uint4*)(Klo + row * STRQ + ch) = *(const uint4*)(g_klo + gk);
    }
    __syncthreads();

    const int wm = (wid >> 2) * 64, wn = (wid & 3) * 32;
    float c[4][4][4];
#pragma unroll
    for (int mi = 0; mi < 4; mi++)
#pragma unroll
        for (int nj = 0; nj < 4; nj++)
#pragma unroll
            for (int e = 0; e < 4; e++) c[mi][nj][e] = 0.f;

    const uint32_t abase[3] = {smem_u32(Qhi), smem_u32(Qlo), smem_u32(Qhi)};
    const uint32_t bbase[3] = {smem_u32(Khi), smem_u32(Khi), smem_u32(Klo)};
    const int arow = lane & 15;
    const int acol = (lane >> 4) * 8;

#pragma unroll
    for (int s = 0; s < 3; s++) {
        const uint32_t ab = abase[s], bb = bbase[s];
#pragma unroll
        for (int k16 = 0; k16 < 8; k16++) {
            const int kc = k16 * 16 + acol;
            uint32_t a[4][4], b[2][4];
#pragma unroll
            for (int mi = 0; mi < 4; mi++)
                ldsm4(a[mi], ab + ((wm + mi * 16 + arow) * STRQ + kc) * 2);
#pragma unroll
            for (int nj = 0; nj < 2; nj++)
                ldsm4(b[nj], bb + ((wn + nj * 16 + arow) * STRQ + kc) * 2);
#pragma unroll
            for (int mi = 0; mi < 4; mi++)
#pragma unroll
                for (int n8 = 0; n8 < 4; n8++)
                    mma16816(c[mi][n8], a[mi], b[n8 >> 1][n8 & 1], b[n8 >> 1][(n8 & 1) + 2]);
        }
    }

    // exp in place
#pragma unroll
    for (int mi = 0; mi < 4; mi++)
#pragma unroll
        for (int n8 = 0; n8 < 4; n8++)
#pragma unroll
            for (int e = 0; e < 4; e++) c[mi][n8][e] = __expf(c[mi][n8][e]);

    // store unnormalized e
    const int r0 = lane >> 2, c0 = (lane & 3) * 2;
#pragma unroll
    for (int mi = 0; mi < 4; mi++) {
#pragma unroll
        for (int n8 = 0; n8 < 4; n8++) {
            size_t row = (size_t)(m0 + wm + mi * 16 + r0);
            size_t col = (size_t)(n0 + wn + n8 * 8 + c0);
            *(float2*)(att + row * LK + col) = make_float2(c[mi][n8][0], c[mi][n8][1]);
            *(float2*)(att + (row + 8) * LK + col) = make_float2(c[mi][n8][2], c[mi][n8][3]);
        }
    }

    // deterministic per-row partial sums over this 128-col block
    __syncthreads();                 // done reading Q/K smem
    float* rs = (float*)smem;        // [128][4]
#pragma unroll
    for (int mi = 0; mi < 4; mi++) {
        float v0 = 0.f, v1 = 0.f;
#pragma unroll
        for (int n8 = 0; n8 < 4; n8++) {
            v0 += c[mi][n8][0] + c[mi][n8][1];
            v1 += c[mi][n8][2] + c[mi][n8][3];
        }
        v0 += __shfl_xor_sync(0xffffffffu, v0, 1);
        v0 += __shfl_xor_sync(0xffffffffu, v0, 2);
        v1 += __shfl_xor_sync(0xffffffffu, v1, 1);
        v1 += __shfl_xor_sync(0xffffffffu, v1, 2);
        if ((lane & 3) == 0) {
            int r = wm + mi * 16 + (lane >> 2);
            rs[r * 4 + (wid & 3)] = v0;
            rs[(r + 8) * 4 + (wid & 3)] = v1;
        }
    }
    __syncthreads();
    if (tid < 128) {
        float s = rs[tid * 4] + rs[tid * 4 + 1] + rs[tid * 4 + 2] + rs[tid * 4 + 3];
        g_lpart[(size_t)(m0 + tid) * 64 + blockIdx.x] = s;
    }
}

// ---------------------------------------------------------------------------
// Kernel B: l = sum of partials (fixed order), store 1/l.
// ---------------------------------------------------------------------------
__global__ __launch_bounds__(256) void lred_kernel() {
    const int row = blockIdx.x * 256 + threadIdx.x;
    const float4* p = (const float4*)(g_lpart + (size_t)row * 64);
    float s = 0.f;
#pragma unroll
    for (int i = 0; i < 16; i++) {
        float4 v = p[i];
        s += v.x + v.y + v.z + v.w;
    }
    g_il[row] = 1.0f / s;
}

// ---------------------------------------------------------------------------
// Kernel C: att = e * il (write back normalized) + partial O = P @ V.
// CTA = 64 q x 128 d, k-chunk = 1024, 16 iters of 64k. Double-buffered V via
// cp.async; S prefetched in regs; 2 CTAs/SM.
// ---------------------------------------------------------------------------
__global__ __launch_bounds__(256, 2) void pv_hmma_kernel(float* __restrict__ att) {
    extern __shared__ __align__(16) char smem[];
    __nv_bfloat16* Phi = (__nv_bfloat16*)smem;            // [64][STRP]
    __nv_bfloat16* Plo = Phi + 64 * STRP;
    __nv_bfloat16* Vb = Plo + 64 * STRP;                  // [2 buf][2 hi/lo][128*STRP]
    float* ilrow = (float*)(Vb + 4 * 128 * STRP);         // [64]

    const int tid = threadIdx.x, lane = tid & 31, wid = tid >> 5;
    const int q0 = blockIdx.y * 64;
    const int kcnk = blockIdx.x;
    const int kbase = kcnk * (LK / KCH);

    if (tid < 64) ilrow[tid] = g_il[q0 + tid];

    const uint32_t vsb = smem_u32(Vb);
    const int VBUF = 2 * 128 * STRP * 2;   // bytes per buffer (hi+lo)
    const int VLO = 128 * STRP * 2;        // lo offset within buffer

    // prefetch V(0)
    {
#pragma unroll
        for (int i = 0; i < 4; i++) {
            int idx = i * 256 + tid;
            int row = idx >> 3, seg = idx & 7;
            cpasync16(vsb + row * (STRP * 2) + seg * 16,
                      g_vthi + (size_t)row * LK + kbase + seg * 8);
        }
#pragma unroll
        for (int i = 0; i < 4; i++) {
            int idx = i * 256 + tid;
            int row = idx >> 3, seg = idx & 7;
            cpasync16(vsb + VLO + row * (STRP * 2) + seg * 16,
                      g_vtlo + (size_t)row * LK + kbase + seg * 8);
        }
        CP_COMMIT();
    }

    // prefetch S(0) into regs
    float4 sreg[2][4];
    {
#pragma unroll
        for (int i = 0; i < 4; i++) {
            int idx = i * 256 + tid;
            int row = idx >> 4, col4 = (idx & 15) * 4;
            sreg[0][i] = *(const float4*)(att + (size_t)(q0 + row) * LK + kbase + col4);
        }
    }
    __syncthreads();   // ilrow visible

    const int wq = (wid >> 2) * 32, wd = (wid & 3) * 32;
    float c[2][4][4];
#pragma unroll
    for (int mi = 0; mi < 2; mi++)
#pragma unroll
        for (int nj = 0; nj < 4; nj++)
#pragma unroll
            for (int e = 0; e < 4; e++) c[mi][nj][e] = 0.f;

    const uint32_t phib = smem_u32(Phi), plob = smem_u32(Plo);
    const int arow = lane & 15;
    const int acol = (lane >> 4) * 8;

#pragma unroll 2
    for (int t = 0; t < 16; t++) {
        const int cur = t & 1, nxt = cur ^ 1;
        const int kb = kbase + t * 64;

        if (t < 15) {
            const int kbn = kb + 64;
            // prefetch S(t+1)
#pragma unroll
            for (int i = 0; i < 4; i++) {
                int idx = i * 256 + tid;
                int row = idx >> 4, col4 = (idx & 15) * 4;
                sreg[nxt][i] = *(const float4*)(att + (size_t)(q0 + row) * LK + kbn + col4);
            }
            // prefetch V(t+1)
            const uint32_t vb = vsb + nxt * VBUF;
#pragma unroll
            for (int i = 0; i < 4; i++) {
                int idx = i * 256 + tid;
                int row = idx >> 3, seg = idx & 7;
                cpasync16(vb + row * (STRP * 2) + seg * 16,
                          g_vthi + (size_t)row * LK + kbn + seg * 8);
            }
#pragma unroll
            for (int i = 0; i < 4; i++) {
                int idx = i * 256 + tid;
                int row = idx >> 3, seg = idx & 7;
                cpasync16(vb + VLO + row * (STRP * 2) + seg * 16,
                          g_vtlo + (size_t)row * LK + kbn + seg * 8);
            }
            CP_COMMIT();
        }

        // process S(t): normalize, write att, stage bf16 hi/lo
#pragma unroll
        for (int i = 0; i < 4; i++) {
            int idx = i * 256 + tid;
            int row = idx >> 4, col4 = (idx & 15) * 4;
            float4 s = sreg[cur][i];
            const float il = ilrow[row];
            float4 p;
            p.x = s.x * il; p.y = s.y * il; p.z = s.z * il; p.w = s.w * il;
            *(float4*)(att + (size_t)(q0 + row) * LK + kb + col4) = p;
            __nv_bfloat162 h01, h23, l01, l23;
            h01.x = __float2bfloat16(p.x);
            h01.y = __float2bfloat16(p.y);
            h23.x = __float2bfloat16(p.z);
            h23.y = __float2bfloat16(p.w);
            l01.x = __float2bfloat16(p.x - __bfloat162float(h01.x));
            l01.y = __float2bfloat16(p.y - __bfloat162float(h01.y));
            l23.x = __float2bfloat16(p.z - __bfloat162float(h23.x));
            l23.y = __float2bfloat16(p.w - __bfloat162float(h23.y));
            *(__nv_bfloat162*)(Phi + row * STRP + col4) = h01;
            *(__nv_bfloat162*)(Phi + row * STRP + col4 + 2) = h23;
            *(__nv_bfloat162*)(Plo + row * STRP + col4) = l01;
            *(__nv_bfloat162*)(Plo + row * STRP + col4 + 2) = l23;
        }

        if (t < 15) { CP_WAIT(1); } else { CP_WAIT(0); }
        __syncthreads();

        // MMA over this 64-k tile
        const uint32_t vhib = vsb + cur * VBUF;
        const uint32_t vlob = vhib + VLO;
        const uint32_t ab3[3] = {phib, plob, phib};
        const uint32_t bb3[3] = {vhib, vhib, vlob};
#pragma unroll
        for (int s = 0; s < 3; s++) {
            const uint32_t ab = ab3[s], bb = bb3[s];
#pragma unroll
            for (int k16 = 0; k16 < 4; k16++) {
                const int kc = k16 * 16 + acol;
                uint32_t a[2][4], b[2][4];
#pragma unroll
                for (int mi = 0; mi < 2; mi++)
                    ldsm4(a[mi], ab + ((wq + mi * 16 + arow) * STRP + kc) * 2);
#pragma unroll
                for (int nj = 0; nj < 2; nj++)
                    ldsm4(b[nj], bb + ((wd + nj * 16 + arow) * STRP + kc) * 2);
#pragma unroll
                for (int mi = 0; mi < 2; mi++)
#pragma unroll
                    for (int n8 = 0; n8 < 4; n8++)
                        mma16816(c[mi][n8], a[mi], b[n8 >> 1][n8 & 1], b[n8 >> 1][(n8 & 1) + 2]);
            }
        }
        __syncthreads();
    }

    float* op = g_opart + (size_t)kcnk * ((size_t)LQ * DIM);
    const int r0 = lane >> 2, c0 = (lane & 3) * 2;
#pragma unroll
    for (int mi = 0; mi < 2; mi++) {
#pragma unroll
        for (int n8 = 0; n8 < 4; n8++) {
            size_t row = (size_t)(q0 + wq + mi * 16 + r0);
            size_t col = (size_t)(wd + n8 * 8 + c0);
            *(float2*)(op + row * DIM + col) = make_float2(c[mi][n8][0], c[mi][n8][1]);
            *(float2*)(op + (row + 8) * DIM + col) = make_float2(c[mi][n8][2], c[mi][n8][3]);
        }
    }
}

// ---------------------------------------------------------------------------
// Kernel D: reduce KCH partials into out
// ---------------------------------------------------------------------------
__global__ __launch_bounds__(256) void reduce_kernel(float* __restrict__ out) {
    const size_t i = (size_t)blockIdx.x * 256 + threadIdx.x;
    float s = 0.f;
#pragma unroll
    for (int c = 0; c < KCH; c++) s += g_opart[(size_t)c * LQ * DIM + i];
    out[i] = s;
}

// ---------------------------------------------------------------------------
extern "C" void kernel_launch(void* const* d_in, const int* in_sizes, int n_in,
                              void* d_out, int out_size) {
    const float* Q = (const float*)d_in[0];
    const float* K = (const float*)d_in[1];
    const float* V = (const float*)d_in[2];
    float* out = (float*)d_out;             // [LQ, DIM]
    float* att = out + (size_t)LQ * DIM;    // [LQ, LK]

    const int smemA = 4 * 128 * STRQ * 2;                                  // 139264
    const int smemC = (2 * 64 * STRP + 4 * 128 * STRP) * 2 + 64 * 4;       // 92416
    cudaFuncSetAttribute(qk_hmma_kernel, cudaFuncAttributeMaxDynamicSharedMemorySize, smemA);
    cudaFuncSetAttribute(pv_hmma_kernel, cudaFuncAttributeMaxDynamicSharedMemorySize, smemC);

    prep_kernel<<<(LQ * DIM) / 256, 256>>>(Q, K, V);
    qk_hmma_kernel<<<dim3(LK / 128, LQ / 128), 256, smemA>>>(att);
    lred_kernel<<<LQ / 256, 256>>>();
    pv_hmma_kernel<<<dim3(KCH, LQ / 64), 256, smemC>>>(att);
    reduce_kernel<<<(LQ * DIM) / 256, 256>>>(out);
}

// round 6
// speedup vs baseline: 3.0568x; 1.4222x over previous
#include <cuda_runtime.h>
#include <cuda_fp16.h>
#include <cstdint>
#include <math.h>

#define LQ 8192
#define LK 8192
#define DIM 128
#define KCH 8
#define SCALE 0.08838834764831845f  // 1/sqrt(128)

#define STRQ 136  // fp16 elems per smem row for 128-wide tiles (272B = 17*16B, conflict-free)
#define STRP 72   // fp16 elems per smem row for 64-wide tiles (144B = 9*16B, conflict-free)

// ---------------- device scratch ----------------
__device__ __half g_qh[(size_t)LQ * DIM], g_ql[(size_t)LQ * DIM];
__device__ __half g_kh[(size_t)LK * DIM];
__device__ __half g_vth[(size_t)DIM * LK];          // V^T hi [d][k]
__device__ float g_lpart[(size_t)LQ * 64];
__device__ float g_il[LQ];
__device__ float g_opart[(size_t)KCH * LQ * DIM];

// ---------------- helpers ----------------
__device__ __forceinline__ uint32_t smem_u32(const void* p) {
    uint32_t a;
    asm("{ .reg .u64 t; cvta.to.shared.u64 t, %1; cvt.u32.u64 %0, t; }" : "=r"(a) : "l"(p));
    return a;
}
__device__ __forceinline__ void ldsm4(uint32_t (&r)[4], uint32_t addr) {
    asm volatile("ldmatrix.sync.aligned.m8n8.x4.shared.b16 {%0,%1,%2,%3}, [%4];"
        : "=r"(r[0]), "=r"(r[1]), "=r"(r[2]), "=r"(r[3]) : "r"(addr));
}
__device__ __forceinline__ void mma16816(float (&c)[4], const uint32_t (&a)[4],
                                         uint32_t b0, uint32_t b1) {
    asm volatile("mma.sync.aligned.m16n8k16.row.col.f32.f16.f16.f32 "
        "{%0,%1,%2,%3}, {%4,%5,%6,%7}, {%8,%9}, {%0,%1,%2,%3};"
        : "+f"(c[0]), "+f"(c[1]), "+f"(c[2]), "+f"(c[3])
        : "r"(a[0]), "r"(a[1]), "r"(a[2]), "r"(a[3]), "r"(b0), "r"(b1));
}
__device__ __forceinline__ void cpasync16(uint32_t dst, const void* src) {
    asm volatile("cp.async.cg.shared.global [%0], [%1], 16;" :: "r"(dst), "l"(src));
}
#define CP_COMMIT() asm volatile("cp.async.commit_group;" ::: "memory")
#define CP_WAIT(N)  asm volatile("cp.async.wait_group %0;" :: "n"(N) : "memory")

// ---------------------------------------------------------------------------
// prep: fp32 -> fp16 hi/lo (Q), hi (K), transposed hi (V); Q prescaled
// ---------------------------------------------------------------------------
__global__ __launch_bounds__(256) void prep_kernel(const float* __restrict__ Q,
                                                   const float* __restrict__ K,
                                                   const float* __restrict__ V) {
    size_t i = (size_t)blockIdx.x * 256 + threadIdx.x;
    float q = Q[i] * SCALE;
    __half qh = __float2half_rn(q);
    g_qh[i] = qh;
    g_ql[i] = __float2half_rn(q - __half2float(qh));
    g_kh[i] = __float2half_rn(K[i]);
    size_t kr = i >> 7, d = i & 127;
    g_vth[d * LK + kr] = __float2half_rn(V[i]);
}

// ---------------------------------------------------------------------------
// Kernel A: e = exp(Qs @ K^T) + per-row partial sums. 64m x 128n per CTA.
// 2-term fp16 split: qh@kh + ql@kh.
// ---------------------------------------------------------------------------
__global__ __launch_bounds__(256, 2) void qk_hmma_kernel(float* __restrict__ att) {
    extern __shared__ __align__(16) char smem[];
    __half* Qh = (__half*)smem;            // [64][STRQ]
    __half* Ql = Qh + 64 * STRQ;
    __half* Kh = Ql + 64 * STRQ;           // [128][STRQ]

    const int tid = threadIdx.x, lane = tid & 31, wid = tid >> 5;
    const int m0 = blockIdx.y * 64, n0 = blockIdx.x * 128;

    const uint32_t qhb = smem_u32(Qh), qlb = smem_u32(Ql), khb = smem_u32(Kh);

    // async one-shot tile loads (16B chunks)
#pragma unroll
    for (int i = 0; i < 4; i++) {           // Qh: 64 rows x 16 segs
        int idx = i * 256 + tid;
        int row = idx >> 4, seg = idx & 15;
        cpasync16(qhb + row * 272 + seg * 16, g_qh + (size_t)(m0 + row) * DIM + seg * 8);
    }
#pragma unroll
    for (int i = 0; i < 4; i++) {           // Ql
        int idx = i * 256 + tid;
        int row = idx >> 4, seg = idx & 15;
        cpasync16(qlb + row * 272 + seg * 16, g_ql + (size_t)(m0 + row) * DIM + seg * 8);
    }
#pragma unroll
    for (int i = 0; i < 8; i++) {           // Kh: 128 rows x 16 segs
        int idx = i * 256 + tid;
        int row = idx >> 4, seg = idx & 15;
        cpasync16(khb + row * 272 + seg * 16, g_kh + (size_t)(n0 + row) * DIM + seg * 8);
    }
    CP_COMMIT();
    CP_WAIT(0);
    __syncthreads();

    const int wm = (wid >> 2) * 32, wn = (wid & 3) * 32;
    float c[2][4][4];
#pragma unroll
    for (int mi = 0; mi < 2; mi++)
#pragma unroll
        for (int nj = 0; nj < 4; nj++)
#pragma unroll
            for (int e = 0; e < 4; e++) c[mi][nj][e] = 0.f;

    const int arow = lane & 15;
    const int acol = (lane >> 4) * 8;

#pragma unroll
    for (int k16 = 0; k16 < 8; k16++) {
        const int kc = k16 * 16 + acol;
        uint32_t a[2][4], b[2][4];
#pragma unroll
        for (int nj = 0; nj < 2; nj++)
            ldsm4(b[nj], khb + ((wn + nj * 16 + arow) * STRQ + kc) * 2);
        // term 1: qh @ kh
#pragma unroll
        for (int mi = 0; mi < 2; mi++)
            ldsm4(a[mi], qhb + ((wm + mi * 16 + arow) * STRQ + kc) * 2);
#pragma unroll
        for (int mi = 0; mi < 2; mi++)
#pragma unroll
            for (int n8 = 0; n8 < 4; n8++)
                mma16816(c[mi][n8], a[mi], b[n8 >> 1][n8 & 1], b[n8 >> 1][(n8 & 1) + 2]);
        // term 2: ql @ kh
#pragma unroll
        for (int mi = 0; mi < 2; mi++)
            ldsm4(a[mi], qlb + ((wm + mi * 16 + arow) * STRQ + kc) * 2);
#pragma unroll
        for (int mi = 0; mi < 2; mi++)
#pragma unroll
            for (int n8 = 0; n8 < 4; n8++)
                mma16816(c[mi][n8], a[mi], b[n8 >> 1][n8 & 1], b[n8 >> 1][(n8 & 1) + 2]);
    }

    // exp in place
#pragma unroll
    for (int mi = 0; mi < 2; mi++)
#pragma unroll
        for (int n8 = 0; n8 < 4; n8++)
#pragma unroll
            for (int e = 0; e < 4; e++) c[mi][n8][e] = __expf(c[mi][n8][e]);

    // store unnormalized e
    const int r0 = lane >> 2, c0 = (lane & 3) * 2;
#pragma unroll
    for (int mi = 0; mi < 2; mi++) {
#pragma unroll
        for (int n8 = 0; n8 < 4; n8++) {
            size_t row = (size_t)(m0 + wm + mi * 16 + r0);
            size_t col = (size_t)(n0 + wn + n8 * 8 + c0);
            *(float2*)(att + row * LK + col) = make_float2(c[mi][n8][0], c[mi][n8][1]);
            *(float2*)(att + (row + 8) * LK + col) = make_float2(c[mi][n8][2], c[mi][n8][3]);
        }
    }

    // deterministic per-row partial sums over this 128-col block
    __syncthreads();
    float* rs = (float*)smem;  // [64][4]
#pragma unroll
    for (int mi = 0; mi < 2; mi++) {
        float v0 = 0.f, v1 = 0.f;
#pragma unroll
        for (int n8 = 0; n8 < 4; n8++) {
            v0 += c[mi][n8][0] + c[mi][n8][1];
            v1 += c[mi][n8][2] + c[mi][n8][3];
        }
        v0 += __shfl_xor_sync(0xffffffffu, v0, 1);
        v0 += __shfl_xor_sync(0xffffffffu, v0, 2);
        v1 += __shfl_xor_sync(0xffffffffu, v1, 1);
        v1 += __shfl_xor_sync(0xffffffffu, v1, 2);
        if ((lane & 3) == 0) {
            int r = wm + mi * 16 + (lane >> 2);
            rs[r * 4 + (wid & 3)] = v0;
            rs[(r + 8) * 4 + (wid & 3)] = v1;
        }
    }
    __syncthreads();
    if (tid < 64) {
        float s = rs[tid * 4] + rs[tid * 4 + 1] + rs[tid * 4 + 2] + rs[tid * 4 + 3];
        g_lpart[(size_t)(m0 + tid) * 64 + blockIdx.x] = s;
    }
}

// ---------------------------------------------------------------------------
// Kernel B: l = sum of partials (fixed order), store 1/l.
// ---------------------------------------------------------------------------
__global__ __launch_bounds__(256) void lred_kernel() {
    const int row = blockIdx.x * 256 + threadIdx.x;
    const float4* p = (const float4*)(g_lpart + (size_t)row * 64);
    float s = 0.f;
#pragma unroll
    for (int i = 0; i < 16; i++) {
        float4 v = p[i];
        s += v.x + v.y + v.z + v.w;
    }
    g_il[row] = 1.0f / s;
}

// ---------------------------------------------------------------------------
// Kernel C: att = e*il in place + partial O = P @ V via fp16 HMMA.
// CTA 64q x 128d, 16 iters of k=64. V hi 4-buffer ring (1 barrier/iter),
// P hi/lo double-buffered, S prefetched in regs. 2 CTAs/SM.
// ---------------------------------------------------------------------------
__global__ __launch_bounds__(256, 2) void pv_hmma_kernel(float* __restrict__ att) {
    extern __shared__ __align__(16) char smem[];
    __half* Pb = (__half*)smem;                       // [2 buf][2 planes][64*STRP]
    __half* Vb = Pb + 2 * 2 * 64 * STRP;              // [4 buf][128*STRP]
    float* ilrow = (float*)(Vb + 4 * 128 * STRP);     // [64]

    const int tid = threadIdx.x, lane = tid & 31, wid = tid >> 5;
    const int q0 = blockIdx.y * 64;
    const int kcnk = blockIdx.x;
    const int kbase = kcnk * (LK / KCH);

    if (tid < 64) ilrow[tid] = g_il[q0 + tid];

    const uint32_t pb = smem_u32(Pb), vb = smem_u32(Vb);
    const int PBUF = 2 * 64 * STRP * 2;   // bytes per P buffer (hi+lo)
    const int PLO = 64 * STRP * 2;
    const int VBUF = 128 * STRP * 2;      // bytes per V buffer

    // prologue: V(0), V(1) as groups 0,1
#pragma unroll
    for (int i = 0; i < 4; i++) {
        int idx = i * 256 + tid;
        int row = idx >> 3, seg = idx & 7;
        cpasync16(vb + row * (STRP * 2) + seg * 16,
                  g_vth + (size_t)row * LK + kbase + seg * 8);
    }
    CP_COMMIT();
#pragma unroll
    for (int i = 0; i < 4; i++) {
        int idx = i * 256 + tid;
        int row = idx >> 3, seg = idx & 7;
        cpasync16(vb + VBUF + row * (STRP * 2) + seg * 16,
                  g_vth + (size_t)row * LK + kbase + 64 + seg * 8);
    }
    CP_COMMIT();

    float4 sreg[2][4];
#pragma unroll
    for (int i = 0; i < 4; i++) {
        int idx = i * 256 + tid;
        int row = idx >> 4, col4 = (idx & 15) * 4;
        sreg[0][i] = *(const float4*)(att + (size_t)(q0 + row) * LK + kbase + col4);
    }
    __syncthreads();   // ilrow visible

    const int wq = (wid >> 2) * 32, wd = (wid & 3) * 32;
    float c[2][4][4];
#pragma unroll
    for (int mi = 0; mi < 2; mi++)
#pragma unroll
        for (int nj = 0; nj < 4; nj++)
#pragma unroll
            for (int e = 0; e < 4; e++) c[mi][nj][e] = 0.f;

    const int arow = lane & 15;
    const int acol = (lane >> 4) * 8;

    for (int t = 0; t < 16; t++) {
        const int cur = t & 1;
        const int kb = kbase + t * 64;

        // 1. prefetch S(t+1)
        if (t < 15) {
#pragma unroll
            for (int i = 0; i < 4; i++) {
                int idx = i * 256 + tid;
                int row = idx >> 4, col4 = (idx & 15) * 4;
                sreg[cur ^ 1][i] = *(const float4*)(att + (size_t)(q0 + row) * LK + kb + 64 + col4);
            }
        }

        // 2. stage P(t): normalize, write att, fp16 hi/lo -> pbuf(cur)
        const uint32_t pcur = pb + cur * PBUF;
#pragma unroll
        for (int i = 0; i < 4; i++) {
            int idx = i * 256 + tid;
            int row = idx >> 4, col4 = (idx & 15) * 4;
            float4 s = sreg[cur][i];
            const float il = ilrow[row];
            float4 p;
            p.x = s.x * il; p.y = s.y * il; p.z = s.z * il; p.w = s.w * il;
            *(float4*)(att + (size_t)(q0 + row) * LK + kb + col4) = p;
            __half2 h01, h23, l01, l23;
            h01.x = __float2half_rn(p.x);
            h01.y = __float2half_rn(p.y);
            h23.x = __float2half_rn(p.z);
            h23.y = __float2half_rn(p.w);
            l01.x = __float2half_rn(p.x - __half2float(h01.x));
            l01.y = __float2half_rn(p.y - __half2float(h01.y));
            l23.x = __float2half_rn(p.z - __half2float(h23.x));
            l23.y = __float2half_rn(p.w - __half2float(h23.y));
            uint32_t po = pcur + (row * STRP + col4) * 2;
            *(__half2*)(smem + (po - smem_u32(smem)) + 0) = h01;     // via direct ptr below
            // (use pointer arithmetic on Pb for clarity)
            __half* dst_hi = Pb + cur * (2 * 64 * STRP) + row * STRP + col4;
            __half* dst_lo = dst_hi + 64 * STRP;
            *(__half2*)(dst_hi) = h01;
            *(__half2*)(dst_hi + 2) = h23;
            *(__half2*)(dst_lo) = l01;
            *(__half2*)(dst_lo + 2) = l23;
        }

        // 3. V(t+2) into ring slot (t+2)&3 — safe: last read at MMA(t-2), fenced by barrier(t-1)
        if (t < 14) {
            const uint32_t vdst = vb + ((t + 2) & 3) * VBUF;
            const int kbn = kb + 128;
#pragma unroll
            for (int i = 0; i < 4; i++) {
                int idx = i * 256 + tid;
                int row = idx >> 3, seg = idx & 7;
                cpasync16(vdst + row * (STRP * 2) + seg * 16,
                          g_vth + (size_t)row * LK + kbn + seg * 8);
            }
        }
        CP_COMMIT();   // always commit (possibly empty) -> group t+2

        // 4. wait for V(t)  (<=2 groups pending: t+1, t+2)
        CP_WAIT(2);
        __syncthreads();

        // 5. MMA(t): 2 terms (ph@vh, pl@vh)
        const uint32_t phib = pb + cur * PBUF;
        const uint32_t plob = phib + PLO;
        const uint32_t vcur = vb + (t & 3) * VBUF;
#pragma unroll
        for (int k16 = 0; k16 < 4; k16++) {
            const int kc = k16 * 16 + acol;
            uint32_t a[2][4], b[2][4];
#pragma unroll
            for (int nj = 0; nj < 2; nj++)
                ldsm4(b[nj], vcur + ((wd + nj * 16 + arow) * STRP + kc) * 2);
#pragma unroll
            for (int mi = 0; mi < 2; mi++)
                ldsm4(a[mi], phib + ((wq + mi * 16 + arow) * STRP + kc) * 2);
#pragma unroll
            for (int mi = 0; mi < 2; mi++)
#pragma unroll
                for (int n8 = 0; n8 < 4; n8++)
                    mma16816(c[mi][n8], a[mi], b[n8 >> 1][n8 & 1], b[n8 >> 1][(n8 & 1) + 2]);
#pragma unroll
            for (int mi = 0; mi < 2; mi++)
                ldsm4(a[mi], plob + ((wq + mi * 16 + arow) * STRP + kc) * 2);
#pragma unroll
            for (int mi = 0; mi < 2; mi++)
#pragma unroll
                for (int n8 = 0; n8 < 4; n8++)
                    mma16816(c[mi][n8], a[mi], b[n8 >> 1][n8 & 1], b[n8 >> 1][(n8 & 1) + 2]);
        }
    }

    float* op = g_opart + (size_t)kcnk * ((size_t)LQ * DIM);
    const int r0 = lane >> 2, c0 = (lane & 3) * 2;
#pragma unroll
    for (int mi = 0; mi < 2; mi++) {
#pragma unroll
        for (int n8 = 0; n8 < 4; n8++) {
            size_t row = (size_t)(q0 + wq + mi * 16 + r0);
            size_t col = (size_t)(wd + n8 * 8 + c0);
            *(float2*)(op + row * DIM + col) = make_float2(c[mi][n8][0], c[mi][n8][1]);
            *(float2*)(op + (row + 8) * DIM + col) = make_float2(c[mi][n8][2], c[mi][n8][3]);
        }
    }
}

// ---------------------------------------------------------------------------
// Kernel D: reduce KCH partials into out
// ---------------------------------------------------------------------------
__global__ __launch_bounds__(256) void reduce_kernel(float* __restrict__ out) {
    const size_t i = (size_t)blockIdx.x * 256 + threadIdx.x;
    float s = 0.f;
#pragma unroll
    for (int c = 0; c < KCH; c++) s += g_opart[(size_t)c * LQ * DIM + i];
    out[i] = s;
}

// ---------------------------------------------------------------------------
extern "C" void kernel_launch(void* const* d_in, const int* in_sizes, int n_in,
                              void* d_out, int out_size) {
    const float* Q = (const float*)d_in[0];
    const float* K = (const float*)d_in[1];
    const float* V = (const float*)d_in[2];
    float* out = (float*)d_out;             // [LQ, DIM]
    float* att = out + (size_t)LQ * DIM;    // [LQ, LK]

    const int smemA = (2 * 64 * STRQ + 128 * STRQ) * 2;                 // 69632
    const int smemC = (2 * 2 * 64 * STRP + 4 * 128 * STRP) * 2 + 256;   // 110848
    cudaFuncSetAttribute(qk_hmma_kernel, cudaFuncAttributeMaxDynamicSharedMemorySize, smemA);
    cudaFuncSetAttribute(pv_hmma_kernel, cudaFuncAttributeMaxDynamicSharedMemorySize, smemC);

    prep_kernel<<<(LQ * DIM) / 256, 256>>>(Q, K, V);
    qk_hmma_kernel<<<dim3(LK / 128, LQ / 64), 256, smemA>>>(att);
    lred_kernel<<<LQ / 256, 256>>>();
    pv_hmma_kernel<<<dim3(KCH, LQ / 64), 256, smemC>>>(att);
    reduce_kernel<<<(LQ * DIM) / 256, 256>>>(out);
}

// round 8
// speedup vs baseline: 3.3945x; 1.1105x over previous
#include <cuda_runtime.h>
#include <cuda_fp16.h>
#include <cstdint>
#include <math.h>

#define LQ 8192
#define LK 8192
#define DIM 128
#define KCH 8
#define SCALE 0.08838834764831845f  // 1/sqrt(128)

#define STRQ 136  // fp16 elems per smem row for 128-wide tiles (272B, conflict-free)
#define STRP 72   // fp16 elems per smem row for 64-wide tiles (144B, conflict-free)

// ---------------- device scratch ----------------
__device__ __half g_qh[(size_t)LQ * DIM], g_ql[(size_t)LQ * DIM];
__device__ __half g_kh[(size_t)LK * DIM];
__device__ __half g_vth[(size_t)DIM * LK];          // V^T hi [d][k]
__device__ float g_lpart[(size_t)LQ * 64];
__device__ float g_il[LQ];
__device__ float g_opart[(size_t)KCH * LQ * DIM];

// ---------------- helpers ----------------
__device__ __forceinline__ uint32_t smem_u32(const void* p) {
    uint32_t a;
    asm("{ .reg .u64 t; cvta.to.shared.u64 t, %1; cvt.u32.u64 %0, t; }" : "=r"(a) : "l"(p));
    return a;
}
__device__ __forceinline__ void ldsm4(uint32_t (&r)[4], uint32_t addr) {
    asm volatile("ldmatrix.sync.aligned.m8n8.x4.shared.b16 {%0,%1,%2,%3}, [%4];"
        : "=r"(r[0]), "=r"(r[1]), "=r"(r[2]), "=r"(r[3]) : "r"(addr));
}
__device__ __forceinline__ void mma16816(float (&c)[4], const uint32_t (&a)[4],
                                         uint32_t b0, uint32_t b1) {
    asm volatile("mma.sync.aligned.m16n8k16.row.col.f32.f16.f16.f32 "
        "{%0,%1,%2,%3}, {%4,%5,%6,%7}, {%8,%9}, {%0,%1,%2,%3};"
        : "+f"(c[0]), "+f"(c[1]), "+f"(c[2]), "+f"(c[3])
        : "r"(a[0]), "r"(a[1]), "r"(a[2]), "r"(a[3]), "r"(b0), "r"(b1));
}
__device__ __forceinline__ void cpasync16(uint32_t dst, const void* src) {
    asm volatile("cp.async.cg.shared.global [%0], [%1], 16;" :: "r"(dst), "l"(src));
}
#define CP_COMMIT() asm volatile("cp.async.commit_group;" ::: "memory")
#define CP_WAIT(N)  asm volatile("cp.async.wait_group %0;" :: "n"(N) : "memory")
__device__ __forceinline__ uint32_t h2u(__half2 h) { return *reinterpret_cast<uint32_t*>(&h); }

// ---------------------------------------------------------------------------
// prep: fp32 -> fp16 hi/lo (Q), hi (K), transposed hi (V); Q prescaled
// ---------------------------------------------------------------------------
__global__ __launch_bounds__(256) void prep_kernel(const float* __restrict__ Q,
                                                   const float* __restrict__ K,
                                                   const float* __restrict__ V) {
    size_t i = (size_t)blockIdx.x * 256 + threadIdx.x;
    float q = Q[i] * SCALE;
    __half qh = __float2half_rn(q);
    g_qh[i] = qh;
    g_ql[i] = __float2half_rn(q - __half2float(qh));
    g_kh[i] = __float2half_rn(K[i]);
    size_t kr = i >> 7, d = i & 127;
    g_vth[d * LK + kr] = __float2half_rn(V[i]);
}

// ---------------------------------------------------------------------------
// Kernel A: e = exp(Qs @ K^T) + per-row partial sums. 64m x 128n per CTA.
// (unchanged from R5 — proven)
// ---------------------------------------------------------------------------
__global__ __launch_bounds__(256, 2) void qk_hmma_kernel(float* __restrict__ att) {
    extern __shared__ __align__(16) char smem[];
    __half* Qh = (__half*)smem;            // [64][STRQ]
    __half* Ql = Qh + 64 * STRQ;
    __half* Kh = Ql + 64 * STRQ;           // [128][STRQ]

    const int tid = threadIdx.x, lane = tid & 31, wid = tid >> 5;
    const int m0 = blockIdx.y * 64, n0 = blockIdx.x * 128;

    const uint32_t qhb = smem_u32(Qh), qlb = smem_u32(Ql), khb = smem_u32(Kh);

#pragma unroll
    for (int i = 0; i < 4; i++) {
        int idx = i * 256 + tid;
        int row = idx >> 4, seg = idx & 15;
        cpasync16(qhb + row * 272 + seg * 16, g_qh + (size_t)(m0 + row) * DIM + seg * 8);
    }
#pragma unroll
    for (int i = 0; i < 4; i++) {
        int idx = i * 256 + tid;
        int row = idx >> 4, seg = idx & 15;
        cpasync16(qlb + row * 272 + seg * 16, g_ql + (size_t)(m0 + row) * DIM + seg * 8);
    }
#pragma unroll
    for (int i = 0; i < 8; i++) {
        int idx = i * 256 + tid;
        int row = idx >> 4, seg = idx & 15;
        cpasync16(khb + row * 272 + seg * 16, g_kh + (size_t)(n0 + row) * DIM + seg * 8);
    }
    CP_COMMIT();
    CP_WAIT(0);
    __syncthreads();

    const int wm = (wid >> 2) * 32, wn = (wid & 3) * 32;
    float c[2][4][4];
#pragma unroll
    for (int mi = 0; mi < 2; mi++)
#pragma unroll
        for (int nj = 0; nj < 4; nj++)
#pragma unroll
            for (int e = 0; e < 4; e++) c[mi][nj][e] = 0.f;

    const int arow = lane & 15;
    const int acol = (lane >> 4) * 8;

#pragma unroll
    for (int k16 = 0; k16 < 8; k16++) {
        const int kc = k16 * 16 + acol;
        uint32_t a[2][4], b[2][4];
#pragma unroll
        for (int nj = 0; nj < 2; nj++)
            ldsm4(b[nj], khb + ((wn + nj * 16 + arow) * STRQ + kc) * 2);
#pragma unroll
        for (int mi = 0; mi < 2; mi++)
            ldsm4(a[mi], qhb + ((wm + mi * 16 + arow) * STRQ + kc) * 2);
#pragma unroll
        for (int mi = 0; mi < 2; mi++)
#pragma unroll
            for (int n8 = 0; n8 < 4; n8++)
                mma16816(c[mi][n8], a[mi], b[n8 >> 1][n8 & 1], b[n8 >> 1][(n8 & 1) + 2]);
#pragma unroll
        for (int mi = 0; mi < 2; mi++)
            ldsm4(a[mi], qlb + ((wm + mi * 16 + arow) * STRQ + kc) * 2);
#pragma unroll
        for (int mi = 0; mi < 2; mi++)
#pragma unroll
            for (int n8 = 0; n8 < 4; n8++)
                mma16816(c[mi][n8], a[mi], b[n8 >> 1][n8 & 1], b[n8 >> 1][(n8 & 1) + 2]);
    }

#pragma unroll
    for (int mi = 0; mi < 2; mi++)
#pragma unroll
        for (int n8 = 0; n8 < 4; n8++)
#pragma unroll
            for (int e = 0; e < 4; e++) c[mi][n8][e] = __expf(c[mi][n8][e]);

    const int r0 = lane >> 2, c0 = (lane & 3) * 2;
#pragma unroll
    for (int mi = 0; mi < 2; mi++) {
#pragma unroll
        for (int n8 = 0; n8 < 4; n8++) {
            size_t row = (size_t)(m0 + wm + mi * 16 + r0);
            size_t col = (size_t)(n0 + wn + n8 * 8 + c0);
            *(float2*)(att + row * LK + col) = make_float2(c[mi][n8][0], c[mi][n8][1]);
            *(float2*)(att + (row + 8) * LK + col) = make_float2(c[mi][n8][2], c[mi][n8][3]);
        }
    }

    __syncthreads();
    float* rs = (float*)smem;  // [64][4]
#pragma unroll
    for (int mi = 0; mi < 2; mi++) {
        float v0 = 0.f, v1 = 0.f;
#pragma unroll
        for (int n8 = 0; n8 < 4; n8++) {
            v0 += c[mi][n8][0] + c[mi][n8][1];
            v1 += c[mi][n8][2] + c[mi][n8][3];
        }
        v0 += __shfl_xor_sync(0xffffffffu, v0, 1);
        v0 += __shfl_xor_sync(0xffffffffu, v0, 2);
        v1 += __shfl_xor_sync(0xffffffffu, v1, 1);
        v1 += __shfl_xor_sync(0xffffffffu, v1, 2);
        if ((lane & 3) == 0) {
            int r = wm + mi * 16 + (lane >> 2);
            rs[r * 4 + (wid & 3)] = v0;
            rs[(r + 8) * 4 + (wid & 3)] = v1;
        }
    }
    __syncthreads();
    if (tid < 64) {
        float s = rs[tid * 4] + rs[tid * 4 + 1] + rs[tid * 4 + 2] + rs[tid * 4 + 3];
        g_lpart[(size_t)(m0 + tid) * 64 + blockIdx.x] = s;
    }
}

// ---------------------------------------------------------------------------
// Kernel B: l = sum of partials (fixed order), store 1/l.
// ---------------------------------------------------------------------------
__global__ __launch_bounds__(256) void lred_kernel() {
    const int row = blockIdx.x * 256 + threadIdx.x;
    const float4* p = (const float4*)(g_lpart + (size_t)row * 64);
    float s = 0.f;
#pragma unroll
    for (int i = 0; i < 16; i++) {
        float4 v = p[i];
        s += v.x + v.y + v.z + v.w;
    }
    g_il[row] = 1.0f / s;
}

// ---------------------------------------------------------------------------
// Kernel C (register-direct, race-free): att = e*il in place + partial O = P@V.
// CTA = 128q x 128d, 8 warps; warp w EXCLUSIVELY owns q-rows [w*16, w*16+16)
// across all 128 d — every att element is read/scaled/written by exactly one
// thread. V hi in 3-slot cp.async ring. 16 iters of k=64 per CTA.
// ---------------------------------------------------------------------------
__global__ __launch_bounds__(256, 2) void pv_hmma_kernel(float* __restrict__ att) {
    extern __shared__ __align__(16) char smem[];
    __half* Vb = (__half*)smem;                       // [3][128][STRP]

    const int tid = threadIdx.x, lane = tid & 31, wid = tid >> 5;
    const int q0 = blockIdx.y * 128;
    const int kcnk = blockIdx.x;
    const int kbase = kcnk * (LK / KCH);

    const int qw = q0 + wid * 16;                     // warp's exclusive 16 q-rows
    const int r0 = lane >> 2, c0 = (lane & 3) * 2;
    const int arow = lane & 15, acol = (lane >> 4) * 8;

    const float il0 = g_il[qw + r0];
    const float il1 = g_il[qw + r0 + 8];

    const uint32_t vb = smem_u32(Vb);
    const int VBUF = 128 * STRP * 2;   // bytes per V buffer

    // prologue: V(0), V(1) as groups 0,1
#pragma unroll
    for (int i = 0; i < 4; i++) {
        int idx = i * 256 + tid;
        int row = idx >> 3, seg = idx & 7;
        cpasync16(vb + row * (STRP * 2) + seg * 16,
                  g_vth + (size_t)row * LK + kbase + seg * 8);
    }
    CP_COMMIT();
#pragma unroll
    for (int i = 0; i < 4; i++) {
        int idx = i * 256 + tid;
        int row = idx >> 3, seg = idx & 7;
        cpasync16(vb + VBUF + row * (STRP * 2) + seg * 16,
                  g_vth + (size_t)row * LK + kbase + 64 + seg * 8);
    }
    CP_COMMIT();

    float o[16][4];
#pragma unroll
    for (int nj = 0; nj < 16; nj++)
#pragma unroll
        for (int e = 0; e < 4; e++) o[nj][e] = 0.f;

    for (int t = 0; t < 16; t++) {
        CP_WAIT(1);           // own V(t) writes landed
        __syncthreads();      // all warps past iter t-1; slot (t+2)%3 free

        // prefetch V(t+2) into slot (t+2)%3
        if (t < 14) {
            const uint32_t vdst = vb + ((t + 2) % 3) * VBUF;
            const int kbn = kbase + (t + 2) * 64;
#pragma unroll
            for (int i = 0; i < 4; i++) {
                int idx = i * 256 + tid;
                int row = idx >> 3, seg = idx & 7;
                cpasync16(vdst + row * (STRP * 2) + seg * 16,
                          g_vth + (size_t)row * LK + kbn + seg * 8);
            }
        }
        CP_COMMIT();          // always commit (possibly empty)

        const int kb = kbase + t * 64;
        const uint32_t vcur = vb + (t % 3) * VBUF;

#pragma unroll
        for (int k16 = 0; k16 < 4; k16++) {
            const int cb = kb + k16 * 16 + c0;
            // --- exclusive load + scale + write-back + fp16 hi/lo split ---
            float* p0 = att + (size_t)(qw + r0) * LK + cb;
            float* p1 = att + (size_t)(qw + r0 + 8) * LK + cb;
            float2 s00 = *(float2*)p0;
            float2 s10 = *(float2*)p1;
            float2 s01 = *(float2*)(p0 + 8);
            float2 s11 = *(float2*)(p1 + 8);
            s00.x *= il0; s00.y *= il0; s01.x *= il0; s01.y *= il0;
            s10.x *= il1; s10.y *= il1; s11.x *= il1; s11.y *= il1;
            *(float2*)p0 = s00;
            *(float2*)p1 = s10;
            *(float2*)(p0 + 8) = s01;
            *(float2*)(p1 + 8) = s11;
            uint32_t ah[4], al[4];
            __half2 h0 = __floats2half2_rn(s00.x, s00.y);
            __half2 h1 = __floats2half2_rn(s10.x, s10.y);
            __half2 h2 = __floats2half2_rn(s01.x, s01.y);
            __half2 h3 = __floats2half2_rn(s11.x, s11.y);
            ah[0] = h2u(h0); ah[1] = h2u(h1); ah[2] = h2u(h2); ah[3] = h2u(h3);
            __half2 l0 = __floats2half2_rn(s00.x - __low2float(h0), s00.y - __high2float(h0));
            __half2 l1 = __floats2half2_rn(s10.x - __low2float(h1), s10.y - __high2float(h1));
            __half2 l2 = __floats2half2_rn(s01.x - __low2float(h2), s01.y - __high2float(h2));
            __half2 l3 = __floats2half2_rn(s11.x - __low2float(h3), s11.y - __high2float(h3));
            al[0] = h2u(l0); al[1] = h2u(l1); al[2] = h2u(l2); al[3] = h2u(l3);

            // --- MMA across all d: warp reads whole V tile for this k16 ---
#pragma unroll
            for (int nj = 0; nj < 8; nj++) {
                uint32_t bv[4];
                ldsm4(bv, vcur + ((nj * 16 + arow) * STRP + k16 * 16 + acol) * 2);
                mma16816(o[2 * nj], ah, bv[0], bv[2]);
                mma16816(o[2 * nj], al, bv[0], bv[2]);
                mma16816(o[2 * nj + 1], ah, bv[1], bv[3]);
                mma16816(o[2 * nj + 1], al, bv[1], bv[3]);
            }
        }
    }

    float* op = g_opart + (size_t)kcnk * ((size_t)LQ * DIM);
#pragma unroll
    for (int n8 = 0; n8 < 16; n8++) {
        size_t row = (size_t)(qw + r0);
        size_t col = (size_t)(n8 * 8 + c0);
        *(float2*)(op + row * DIM + col) = make_float2(o[n8][0], o[n8][1]);
        *(float2*)(op + (row + 8) * DIM + col) = make_float2(o[n8][2], o[n8][3]);
    }
}

// ---------------------------------------------------------------------------
// Kernel D: reduce KCH partials into out
// ---------------------------------------------------------------------------
__global__ __launch_bounds__(256) void reduce_kernel(float* __restrict__ out) {
    const size_t i = (size_t)blockIdx.x * 256 + threadIdx.x;
    float s = 0.f;
#pragma unroll
    for (int c = 0; c < KCH; c++) s += g_opart[(size_t)c * LQ * DIM + i];
    out[i] = s;
}

// ---------------------------------------------------------------------------
extern "C" void kernel_launch(void* const* d_in, const int* in_sizes, int n_in,
                              void* d_out, int out_size) {
    const float* Q = (const float*)d_in[0];
    const float* K = (const float*)d_in[1];
    const float* V = (const float*)d_in[2];
    float* out = (float*)d_out;             // [LQ, DIM]
    float* att = out + (size_t)LQ * DIM;    // [LQ, LK]

    const int smemA = (2 * 64 * STRQ + 128 * STRQ) * 2;   // 69632
    const int smemC = 3 * 128 * STRP * 2;                 // 55296
    cudaFuncSetAttribute(qk_hmma_kernel, cudaFuncAttributeMaxDynamicSharedMemorySize, smemA);
    cudaFuncSetAttribute(pv_hmma_kernel, cudaFuncAttributeMaxDynamicSharedMemorySize, smemC);

    prep_kernel<<<(LQ * DIM) / 256, 256>>>(Q, K, V);
    qk_hmma_kernel<<<dim3(LK / 128, LQ / 64), 256, smemA>>>(att);
    lred_kernel<<<LQ / 256, 256>>>();
    pv_hmma_kernel<<<dim3(KCH, LQ / 128), 256, smemC>>>(att);
    reduce_kernel<<<(LQ * DIM) / 256, 256>>>(out);
}

// round 9
// speedup vs baseline: 3.5207x; 1.0372x over previous
#include <cuda_runtime.h>
#include <cuda_fp16.h>
#include <cstdint>
#include <math.h>

#define LQ 8192
#define LK 8192
#define DIM 128
#define KCH 8
#define SCALE 0.08838834764831845f  // 1/sqrt(128)

#define STRQ 136  // fp16 elems per smem row for 128-wide tiles (272B, conflict-free)
#define STRP 72   // fp16 elems per smem row for V tiles (144B)
#define SSTR 72   // fp32 elems per smem row for S tiles (288B)

// ---------------- device scratch ----------------
__device__ __half g_qh[(size_t)LQ * DIM], g_ql[(size_t)LQ * DIM];
__device__ __half g_kh[(size_t)LK * DIM];
__device__ __half g_vth[(size_t)DIM * LK];          // V^T hi [d][k]
__device__ float g_lpart[(size_t)LQ * 64];
__device__ float g_il[LQ];
__device__ float g_opart[(size_t)KCH * LQ * DIM];

// ---------------- helpers ----------------
__device__ __forceinline__ uint32_t smem_u32(const void* p) {
    uint32_t a;
    asm("{ .reg .u64 t; cvta.to.shared.u64 t, %1; cvt.u32.u64 %0, t; }" : "=r"(a) : "l"(p));
    return a;
}
__device__ __forceinline__ void ldsm4(uint32_t (&r)[4], uint32_t addr) {
    asm volatile("ldmatrix.sync.aligned.m8n8.x4.shared.b16 {%0,%1,%2,%3}, [%4];"
        : "=r"(r[0]), "=r"(r[1]), "=r"(r[2]), "=r"(r[3]) : "r"(addr));
}
__device__ __forceinline__ void mma16816(float (&c)[4], const uint32_t (&a)[4],
                                         uint32_t b0, uint32_t b1) {
    asm volatile("mma.sync.aligned.m16n8k16.row.col.f32.f16.f16.f32 "
        "{%0,%1,%2,%3}, {%4,%5,%6,%7}, {%8,%9}, {%0,%1,%2,%3};"
        : "+f"(c[0]), "+f"(c[1]), "+f"(c[2]), "+f"(c[3])
        : "r"(a[0]), "r"(a[1]), "r"(a[2]), "r"(a[3]), "r"(b0), "r"(b1));
}
__device__ __forceinline__ void cpasync16(uint32_t dst, const void* src) {
    asm volatile("cp.async.cg.shared.global [%0], [%1], 16;" :: "r"(dst), "l"(src));
}
#define CP_COMMIT() asm volatile("cp.async.commit_group;" ::: "memory")
#define CP_WAIT(N)  asm volatile("cp.async.wait_group %0;" :: "n"(N) : "memory")
__device__ __forceinline__ uint32_t h2u(__half2 h) { return *reinterpret_cast<uint32_t*>(&h); }

// ---------------------------------------------------------------------------
// prep: fp32 -> fp16 hi/lo (Q), hi (K), transposed hi (V); Q prescaled
// ---------------------------------------------------------------------------
__global__ __launch_bounds__(256) void prep_kernel(const float* __restrict__ Q,
                                                   const float* __restrict__ K,
                                                   const float* __restrict__ V) {
    size_t i = (size_t)blockIdx.x * 256 + threadIdx.x;
    float q = Q[i] * SCALE;
    __half qh = __float2half_rn(q);
    g_qh[i] = qh;
    g_ql[i] = __float2half_rn(q - __half2float(qh));
    g_kh[i] = __float2half_rn(K[i]);
    size_t kr = i >> 7, d = i & 127;
    g_vth[d * LK + kr] = __float2half_rn(V[i]);
}

// ---------------------------------------------------------------------------
// Kernel A: e = exp(Qs @ K^T) + per-row partial sums. 64m x 128n per CTA.
// ---------------------------------------------------------------------------
__global__ __launch_bounds__(256, 2) void qk_hmma_kernel(float* __restrict__ att) {
    extern __shared__ __align__(16) char smem[];
    __half* Qh = (__half*)smem;            // [64][STRQ]
    __half* Ql = Qh + 64 * STRQ;
    __half* Kh = Ql + 64 * STRQ;           // [128][STRQ]

    const int tid = threadIdx.x, lane = tid & 31, wid = tid >> 5;
    const int m0 = blockIdx.y * 64, n0 = blockIdx.x * 128;

    const uint32_t qhb = smem_u32(Qh), qlb = smem_u32(Ql), khb = smem_u32(Kh);

#pragma unroll
    for (int i = 0; i < 4; i++) {
        int idx = i * 256 + tid;
        int row = idx >> 4, seg = idx & 15;
        cpasync16(qhb + row * 272 + seg * 16, g_qh + (size_t)(m0 + row) * DIM + seg * 8);
    }
#pragma unroll
    for (int i = 0; i < 4; i++) {
        int idx = i * 256 + tid;
        int row = idx >> 4, seg = idx & 15;
        cpasync16(qlb + row * 272 + seg * 16, g_ql + (size_t)(m0 + row) * DIM + seg * 8);
    }
#pragma unroll
    for (int i = 0; i < 8; i++) {
        int idx = i * 256 + tid;
        int row = idx >> 4, seg = idx & 15;
        cpasync16(khb + row * 272 + seg * 16, g_kh + (size_t)(n0 + row) * DIM + seg * 8);
    }
    CP_COMMIT();
    CP_WAIT(0);
    __syncthreads();

    const int wm = (wid >> 2) * 32, wn = (wid & 3) * 32;
    float c[2][4][4];
#pragma unroll
    for (int mi = 0; mi < 2; mi++)
#pragma unroll
        for (int nj = 0; nj < 4; nj++)
#pragma unroll
            for (int e = 0; e < 4; e++) c[mi][nj][e] = 0.f;

    const int arow = lane & 15;
    const int acol = (lane >> 4) * 8;

#pragma unroll
    for (int k16 = 0; k16 < 8; k16++) {
        const int kc = k16 * 16 + acol;
        uint32_t a[2][4], b[2][4];
#pragma unroll
        for (int nj = 0; nj < 2; nj++)
            ldsm4(b[nj], khb + ((wn + nj * 16 + arow) * STRQ + kc) * 2);
#pragma unroll
        for (int mi = 0; mi < 2; mi++)
            ldsm4(a[mi], qhb + ((wm + mi * 16 + arow) * STRQ + kc) * 2);
#pragma unroll
        for (int mi = 0; mi < 2; mi++)
#pragma unroll
            for (int n8 = 0; n8 < 4; n8++)
                mma16816(c[mi][n8], a[mi], b[n8 >> 1][n8 & 1], b[n8 >> 1][(n8 & 1) + 2]);
#pragma unroll
        for (int mi = 0; mi < 2; mi++)
            ldsm4(a[mi], qlb + ((wm + mi * 16 + arow) * STRQ + kc) * 2);
#pragma unroll
        for (int mi = 0; mi < 2; mi++)
#pragma unroll
            for (int n8 = 0; n8 < 4; n8++)
                mma16816(c[mi][n8], a[mi], b[n8 >> 1][n8 & 1], b[n8 >> 1][(n8 & 1) + 2]);
    }

#pragma unroll
    for (int mi = 0; mi < 2; mi++)
#pragma unroll
        for (int n8 = 0; n8 < 4; n8++)
#pragma unroll
            for (int e = 0; e < 4; e++) c[mi][n8][e] = __expf(c[mi][n8][e]);

    const int r0 = lane >> 2, c0 = (lane & 3) * 2;
#pragma unroll
    for (int mi = 0; mi < 2; mi++) {
#pragma unroll
        for (int n8 = 0; n8 < 4; n8++) {
            size_t row = (size_t)(m0 + wm + mi * 16 + r0);
            size_t col = (size_t)(n0 + wn + n8 * 8 + c0);
            *(float2*)(att + row * LK + col) = make_float2(c[mi][n8][0], c[mi][n8][1]);
            *(float2*)(att + (row + 8) * LK + col) = make_float2(c[mi][n8][2], c[mi][n8][3]);
        }
    }

    __syncthreads();
    float* rs = (float*)smem;  // [64][4]
#pragma unroll
    for (int mi = 0; mi < 2; mi++) {
        float v0 = 0.f, v1 = 0.f;
#pragma unroll
        for (int n8 = 0; n8 < 4; n8++) {
            v0 += c[mi][n8][0] + c[mi][n8][1];
            v1 += c[mi][n8][2] + c[mi][n8][3];
        }
        v0 += __shfl_xor_sync(0xffffffffu, v0, 1);
        v0 += __shfl_xor_sync(0xffffffffu, v0, 2);
        v1 += __shfl_xor_sync(0xffffffffu, v1, 1);
        v1 += __shfl_xor_sync(0xffffffffu, v1, 2);
        if ((lane & 3) == 0) {
            int r = wm + mi * 16 + (lane >> 2);
            rs[r * 4 + (wid & 3)] = v0;
            rs[(r + 8) * 4 + (wid & 3)] = v1;
        }
    }
    __syncthreads();
    if (tid < 64) {
        float s = rs[tid * 4] + rs[tid * 4 + 1] + rs[tid * 4 + 2] + rs[tid * 4 + 3];
        g_lpart[(size_t)(m0 + tid) * 64 + blockIdx.x] = s;
    }
}

// ---------------------------------------------------------------------------
// Kernel B: l = sum of partials (fixed order), store 1/l.
// ---------------------------------------------------------------------------
__global__ __launch_bounds__(256) void lred_kernel() {
    const int row = blockIdx.x * 256 + threadIdx.x;
    const float4* p = (const float4*)(g_lpart + (size_t)row * 64);
    float s = 0.f;
#pragma unroll
    for (int i = 0; i < 16; i++) {
        float4 v = p[i];
        s += v.x + v.y + v.z + v.w;
    }
    g_il[row] = 1.0f / s;
}

// ---------------------------------------------------------------------------
// Kernel C (smem-pipelined): S and V stream through 3-deep cp.async rings.
// CTA = 512 threads, 128q x 128d; 16 warps in 8q x 2d grid (warp: 16q x 64d).
// att write-back is a disjoint tid-partition (read S smem, scale, STG.128);
// A-frags built from read-only S smem per warp. No races, no exposed LDG.
// ---------------------------------------------------------------------------
__global__ __launch_bounds__(512, 1) void pv_hmma_kernel(float* __restrict__ att) {
    extern __shared__ __align__(16) char smem[];
    float* Ss = (float*)smem;                          // [3][128][SSTR] fp32
    __half* Vs = (__half*)(Ss + 3 * 128 * SSTR);       // [3][128][STRP] fp16
    float* ilrow = (float*)(Vs + 3 * 128 * STRP);      // [128]

    const int tid = threadIdx.x, lane = tid & 31, wid = tid >> 5;
    const int q0 = blockIdx.y * 128;
    const int kcnk = blockIdx.x;
    const int kbase = kcnk * (LK / KCH);

    const int qg = (wid & 7) * 16;          // warp's q-rows within tile
    const int dh = (wid >> 3) * 64;         // warp's d-half
    const int r0 = lane >> 2, c0 = (lane & 3) * 2;
    const int arow = lane & 15, acol = (lane >> 4) * 8;

    if (tid < 128) ilrow[tid] = g_il[q0 + tid];
    const float il0 = g_il[q0 + qg + r0];
    const float il1 = g_il[q0 + qg + r0 + 8];

    const uint32_t sb = smem_u32(Ss), vbb = smem_u32(Vs);
    const int SBUF = 128 * SSTR * 4;   // bytes per S stage
    const int VBUF = 128 * STRP * 2;   // bytes per V stage

    // prologue: stages 0 and 1 as separate groups
#pragma unroll
    for (int st = 0; st < 2; st++) {
        const int kb = kbase + st * 64;
#pragma unroll
        for (int i = 0; i < 4; i++) {                  // S: 128 rows x 16 chunks
            int idx = i * 512 + tid;
            int row = idx >> 4, seg = idx & 15;
            cpasync16(sb + st * SBUF + row * (SSTR * 4) + seg * 16,
                      att + (size_t)(q0 + row) * LK + kb + seg * 4);
        }
#pragma unroll
        for (int i = 0; i < 2; i++) {                  // V: 128 rows x 8 chunks
            int idx = i * 512 + tid;
            int row = idx >> 3, seg = idx & 7;
            cpasync16(vbb + st * VBUF + row * (STRP * 2) + seg * 16,
                      g_vth + (size_t)row * LK + kb + seg * 8);
        }
        CP_COMMIT();
    }

    float o[8][4];
#pragma unroll
    for (int nj = 0; nj < 8; nj++)
#pragma unroll
        for (int e = 0; e < 4; e++) o[nj][e] = 0.f;

    for (int t = 0; t < 16; t++) {
        CP_WAIT(1);           // stage t landed
        __syncthreads();      // all warps done with stage t-1 (slot (t+2)%3 free)

        // prefetch stage t+2
        if (t < 14) {
            const int slot = (t + 2) % 3;
            const int kbn = kbase + (t + 2) * 64;
#pragma unroll
            for (int i = 0; i < 4; i++) {
                int idx = i * 512 + tid;
                int row = idx >> 4, seg = idx & 15;
                cpasync16(sb + slot * SBUF + row * (SSTR * 4) + seg * 16,
                          att + (size_t)(q0 + row) * LK + kbn + seg * 4);
            }
#pragma unroll
            for (int i = 0; i < 2; i++) {
                int idx = i * 512 + tid;
                int row = idx >> 3, seg = idx & 7;
                cpasync16(vbb + slot * VBUF + row * (STRP * 2) + seg * 16,
                          g_vth + (size_t)row * LK + kbn + seg * 8);
            }
        }
        CP_COMMIT();          // always one group per iter

        const int kb = kbase + t * 64;
        const float* Sc = Ss + (t % 3) * 128 * SSTR;
        const uint32_t vcur = vbb + (t % 3) * VBUF;

        // a) normalized att write-back: disjoint tid-partition, float4 stores
#pragma unroll
        for (int i = 0; i < 4; i++) {
            int idx = i * 512 + tid;
            int row = idx >> 4, col4 = (idx & 15) * 4;
            float4 s = *(const float4*)(Sc + row * SSTR + col4);
            const float il = ilrow[row];
            s.x *= il; s.y *= il; s.z *= il; s.w *= il;
            *(float4*)(att + (size_t)(q0 + row) * LK + kb + col4) = s;
        }

        // b) MMA: A-frags from S smem (scale+split in regs), B from V smem
#pragma unroll
        for (int k16 = 0; k16 < 4; k16++) {
            const int kc = k16 * 16 + c0;
            const float* rp0 = Sc + (qg + r0) * SSTR + kc;
            const float* rp1 = Sc + (qg + r0 + 8) * SSTR + kc;
            float2 s00 = *(const float2*)rp0;
            float2 s10 = *(const float2*)rp1;
            float2 s01 = *(const float2*)(rp0 + 8);
            float2 s11 = *(const float2*)(rp1 + 8);
            s00.x *= il0; s00.y *= il0; s01.x *= il0; s01.y *= il0;
            s10.x *= il1; s10.y *= il1; s11.x *= il1; s11.y *= il1;
            uint32_t ah[4], al[4];
            __half2 h0 = __floats2half2_rn(s00.x, s00.y);
            __half2 h1 = __floats2half2_rn(s10.x, s10.y);
            __half2 h2 = __floats2half2_rn(s01.x, s01.y);
            __half2 h3 = __floats2half2_rn(s11.x, s11.y);
            ah[0] = h2u(h0); ah[1] = h2u(h1); ah[2] = h2u(h2); ah[3] = h2u(h3);
            __half2 l0 = __floats2half2_rn(s00.x - __low2float(h0), s00.y - __high2float(h0));
            __half2 l1 = __floats2half2_rn(s10.x - __low2float(h1), s10.y - __high2float(h1));
            __half2 l2 = __floats2half2_rn(s01.x - __low2float(h2), s01.y - __high2float(h2));
            __half2 l3 = __floats2half2_rn(s11.x - __low2float(h3), s11.y - __high2float(h3));
            al[0] = h2u(l0); al[1] = h2u(l1); al[2] = h2u(l2); al[3] = h2u(l3);

#pragma unroll
            for (int nj = 0; nj < 4; nj++) {
                uint32_t bv[4];
                ldsm4(bv, vcur + ((dh + nj * 16 + arow) * STRP + k16 * 16 + acol) * 2);
                mma16816(o[2 * nj], ah, bv[0], bv[2]);
                mma16816(o[2 * nj], al, bv[0], bv[2]);
                mma16816(o[2 * nj + 1], ah, bv[1], bv[3]);
                mma16816(o[2 * nj + 1], al, bv[1], bv[3]);
            }
        }
    }

    float* op = g_opart + (size_t)kcnk * ((size_t)LQ * DIM);
#pragma unroll
    for (int n8 = 0; n8 < 8; n8++) {
        size_t row = (size_t)(q0 + qg + r0);
        size_t col = (size_t)(dh + n8 * 8 + c0);
        *(float2*)(op + row * DIM + col) = make_float2(o[n8][0], o[n8][1]);
        *(float2*)(op + (row + 8) * DIM + col) = make_float2(o[n8][2], o[n8][3]);
    }
}

// ---------------------------------------------------------------------------
// Kernel D: reduce KCH partials into out
// ---------------------------------------------------------------------------
__global__ __launch_bounds__(256) void reduce_kernel(float* __restrict__ out) {
    const size_t i = (size_t)blockIdx.x * 256 + threadIdx.x;
    float s = 0.f;
#pragma unroll
    for (int c = 0; c < KCH; c++) s += g_opart[(size_t)c * LQ * DIM + i];
    out[i] = s;
}

// ---------------------------------------------------------------------------
extern "C" void kernel_launch(void* const* d_in, const int* in_sizes, int n_in,
                              void* d_out, int out_size) {
    const float* Q = (const float*)d_in[0];
    const float* K = (const float*)d_in[1];
    const float* V = (const float*)d_in[2];
    float* out = (float*)d_out;             // [LQ, DIM]
    float* att = out + (size_t)LQ * DIM;    // [LQ, LK]

    const int smemA = (2 * 64 * STRQ + 128 * STRQ) * 2;             // 69632
    const int smemC = 3 * 128 * SSTR * 4 + 3 * 128 * STRP * 2 + 512; // 166400
    cudaFuncSetAttribute(qk_hmma_kernel, cudaFuncAttributeMaxDynamicSharedMemorySize, smemA);
    cudaFuncSetAttribute(pv_hmma_kernel, cudaFuncAttributeMaxDynamicSharedMemorySize, smemC);

    prep_kernel<<<(LQ * DIM) / 256, 256>>>(Q, K, V);
    qk_hmma_kernel<<<dim3(LK / 128, LQ / 64), 256, smemA>>>(att);
    lred_kernel<<<LQ / 256, 256>>>();
    pv_hmma_kernel<<<dim3(KCH, LQ / 128), 512, smemC>>>(att);
    reduce_kernel<<<(LQ * DIM) / 256, 256>>>(out);
}

// round 10
// speedup vs baseline: 4.2971x; 1.2205x over previous
#include <cuda_runtime.h>
#include <cuda_fp16.h>
#include <cstdint>
#include <math.h>

#define LQ 8192
#define LK 8192
#define DIM 128
#define KCH 8
#define SCALE 0.08838834764831845f  // 1/sqrt(128)

#define STRQ 136  // fp16 elems per smem row for 128-wide tiles (272B, conflict-free)
#define STRP 72   // fp16 elems per smem row for V tiles (144B)
#define SSTR 72   // fp32 elems per smem row for S tiles (288B)

// ---------------- device scratch ----------------
__device__ __half g_qh[(size_t)LQ * DIM];
__device__ __half g_kh[(size_t)LK * DIM];
__device__ __half g_vth[(size_t)DIM * LK];          // V^T [d][k]
__device__ float g_lpart[(size_t)LQ * 64];
__device__ float g_il[LQ];
__device__ float g_opart[(size_t)KCH * LQ * DIM];

// ---------------- helpers ----------------
__device__ __forceinline__ uint32_t smem_u32(const void* p) {
    uint32_t a;
    asm("{ .reg .u64 t; cvta.to.shared.u64 t, %1; cvt.u32.u64 %0, t; }" : "=r"(a) : "l"(p));
    return a;
}
__device__ __forceinline__ void ldsm4(uint32_t (&r)[4], uint32_t addr) {
    asm volatile("ldmatrix.sync.aligned.m8n8.x4.shared.b16 {%0,%1,%2,%3}, [%4];"
        : "=r"(r[0]), "=r"(r[1]), "=r"(r[2]), "=r"(r[3]) : "r"(addr));
}
__device__ __forceinline__ void mma16816(float (&c)[4], const uint32_t (&a)[4],
                                         uint32_t b0, uint32_t b1) {
    asm volatile("mma.sync.aligned.m16n8k16.row.col.f32.f16.f16.f32 "
        "{%0,%1,%2,%3}, {%4,%5,%6,%7}, {%8,%9}, {%0,%1,%2,%3};"
        : "+f"(c[0]), "+f"(c[1]), "+f"(c[2]), "+f"(c[3])
        : "r"(a[0]), "r"(a[1]), "r"(a[2]), "r"(a[3]), "r"(b0), "r"(b1));
}
__device__ __forceinline__ void cpasync16(uint32_t dst, const void* src) {
    asm volatile("cp.async.cg.shared.global [%0], [%1], 16;" :: "r"(dst), "l"(src));
}
#define CP_COMMIT() asm volatile("cp.async.commit_group;" ::: "memory")
#define CP_WAIT(N)  asm volatile("cp.async.wait_group %0;" :: "n"(N) : "memory")
__device__ __forceinline__ uint32_t h2u(__half2 h) { return *reinterpret_cast<uint32_t*>(&h); }

// ---------------------------------------------------------------------------
// prep: fp32 -> fp16 (Q prescaled, K, V transposed)
// ---------------------------------------------------------------------------
__global__ __launch_bounds__(256) void prep_kernel(const float* __restrict__ Q,
                                                   const float* __restrict__ K,
                                                   const float* __restrict__ V) {
    size_t i = (size_t)blockIdx.x * 256 + threadIdx.x;
    g_qh[i] = __float2half_rn(Q[i] * SCALE);
    g_kh[i] = __float2half_rn(K[i]);
    size_t kr = i >> 7, d = i & 127;
    g_vth[d * LK + kr] = __float2half_rn(V[i]);
}

// ---------------------------------------------------------------------------
// Kernel A: e = exp(Qs @ K^T) + per-row partial sums. 64m x 128n per CTA.
// Single fp16 term.
// ---------------------------------------------------------------------------
__global__ __launch_bounds__(256, 2) void qk_hmma_kernel(float* __restrict__ att) {
    extern __shared__ __align__(16) char smem[];
    __half* Qh = (__half*)smem;            // [64][STRQ]
    __half* Kh = Qh + 64 * STRQ;           // [128][STRQ]

    const int tid = threadIdx.x, lane = tid & 31, wid = tid >> 5;
    const int m0 = blockIdx.y * 64, n0 = blockIdx.x * 128;

    const uint32_t qhb = smem_u32(Qh), khb = smem_u32(Kh);

#pragma unroll
    for (int i = 0; i < 4; i++) {
        int idx = i * 256 + tid;
        int row = idx >> 4, seg = idx & 15;
        cpasync16(qhb + row * 272 + seg * 16, g_qh + (size_t)(m0 + row) * DIM + seg * 8);
    }
#pragma unroll
    for (int i = 0; i < 8; i++) {
        int idx = i * 256 + tid;
        int row = idx >> 4, seg = idx & 15;
        cpasync16(khb + row * 272 + seg * 16, g_kh + (size_t)(n0 + row) * DIM + seg * 8);
    }
    CP_COMMIT();
    CP_WAIT(0);
    __syncthreads();

    const int wm = (wid >> 2) * 32, wn = (wid & 3) * 32;
    float c[2][4][4];
#pragma unroll
    for (int mi = 0; mi < 2; mi++)
#pragma unroll
        for (int nj = 0; nj < 4; nj++)
#pragma unroll
            for (int e = 0; e < 4; e++) c[mi][nj][e] = 0.f;

    const int arow = lane & 15;
    const int acol = (lane >> 4) * 8;

#pragma unroll
    for (int k16 = 0; k16 < 8; k16++) {
        const int kc = k16 * 16 + acol;
        uint32_t a[2][4], b[2][4];
#pragma unroll
        for (int nj = 0; nj < 2; nj++)
            ldsm4(b[nj], khb + ((wn + nj * 16 + arow) * STRQ + kc) * 2);
#pragma unroll
        for (int mi = 0; mi < 2; mi++)
            ldsm4(a[mi], qhb + ((wm + mi * 16 + arow) * STRQ + kc) * 2);
#pragma unroll
        for (int mi = 0; mi < 2; mi++)
#pragma unroll
            for (int n8 = 0; n8 < 4; n8++)
                mma16816(c[mi][n8], a[mi], b[n8 >> 1][n8 & 1], b[n8 >> 1][(n8 & 1) + 2]);
    }

#pragma unroll
    for (int mi = 0; mi < 2; mi++)
#pragma unroll
        for (int n8 = 0; n8 < 4; n8++)
#pragma unroll
            for (int e = 0; e < 4; e++) c[mi][n8][e] = __expf(c[mi][n8][e]);

    const int r0 = lane >> 2, c0 = (lane & 3) * 2;
#pragma unroll
    for (int mi = 0; mi < 2; mi++) {
#pragma unroll
        for (int n8 = 0; n8 < 4; n8++) {
            size_t row = (size_t)(m0 + wm + mi * 16 + r0);
            size_t col = (size_t)(n0 + wn + n8 * 8 + c0);
            *(float2*)(att + row * LK + col) = make_float2(c[mi][n8][0], c[mi][n8][1]);
            *(float2*)(att + (row + 8) * LK + col) = make_float2(c[mi][n8][2], c[mi][n8][3]);
        }
    }

    __syncthreads();
    float* rs = (float*)smem;  // [64][4]
#pragma unroll
    for (int mi = 0; mi < 2; mi++) {
        float v0 = 0.f, v1 = 0.f;
#pragma unroll
        for (int n8 = 0; n8 < 4; n8++) {
            v0 += c[mi][n8][0] + c[mi][n8][1];
            v1 += c[mi][n8][2] + c[mi][n8][3];
        }
        v0 += __shfl_xor_sync(0xffffffffu, v0, 1);
        v0 += __shfl_xor_sync(0xffffffffu, v0, 2);
        v1 += __shfl_xor_sync(0xffffffffu, v1, 1);
        v1 += __shfl_xor_sync(0xffffffffu, v1, 2);
        if ((lane & 3) == 0) {
            int r = wm + mi * 16 + (lane >> 2);
            rs[r * 4 + (wid & 3)] = v0;
            rs[(r + 8) * 4 + (wid & 3)] = v1;
        }
    }
    __syncthreads();
    if (tid < 64) {
        float s = rs[tid * 4] + rs[tid * 4 + 1] + rs[tid * 4 + 2] + rs[tid * 4 + 3];
        g_lpart[(size_t)(m0 + tid) * 64 + blockIdx.x] = s;
    }
}

// ---------------------------------------------------------------------------
// Kernel B: l = sum of partials (fixed order), store 1/l.
// ---------------------------------------------------------------------------
__global__ __launch_bounds__(256) void lred_kernel() {
    const int row = blockIdx.x * 256 + threadIdx.x;
    const float4* p = (const float4*)(g_lpart + (size_t)row * 64);
    float s = 0.f;
#pragma unroll
    for (int i = 0; i < 16; i++) {
        float4 v = p[i];
        s += v.x + v.y + v.z + v.w;
    }
    g_il[row] = 1.0f / s;
}

// ---------------------------------------------------------------------------
// Kernel C: att = e*il in place + partial Ounnorm = e @ V (single fp16 term;
// normalization folded into reduce). S/V stream through 3-deep cp.async rings.
// CTA = 512 threads, 128q x 128d; 16 warps in 8q x 2d grid.
// ---------------------------------------------------------------------------
__global__ __launch_bounds__(512, 1) void pv_hmma_kernel(float* __restrict__ att) {
    extern __shared__ __align__(16) char smem[];
    float* Ss = (float*)smem;                          // [3][128][SSTR] fp32
    __half* Vs = (__half*)(Ss + 3 * 128 * SSTR);       // [3][128][STRP] fp16
    float* ilrow = (float*)(Vs + 3 * 128 * STRP);      // [128]

    const int tid = threadIdx.x, lane = tid & 31, wid = tid >> 5;
    const int q0 = blockIdx.y * 128;
    const int kcnk = blockIdx.x;
    const int kbase = kcnk * (LK / KCH);

    const int qg = (wid & 7) * 16;          // warp's q-rows within tile
    const int dh = (wid >> 3) * 64;         // warp's d-half
    const int r0 = lane >> 2, c0 = (lane & 3) * 2;
    const int arow = lane & 15, acol = (lane >> 4) * 8;

    if (tid < 128) ilrow[tid] = g_il[q0 + tid];

    const uint32_t sb = smem_u32(Ss), vbb = smem_u32(Vs);
    const int SBUF = 128 * SSTR * 4;
    const int VBUF = 128 * STRP * 2;

    // prologue: stages 0 and 1
#pragma unroll
    for (int st = 0; st < 2; st++) {
        const int kb = kbase + st * 64;
#pragma unroll
        for (int i = 0; i < 4; i++) {
            int idx = i * 512 + tid;
            int row = idx >> 4, seg = idx & 15;
            cpasync16(sb + st * SBUF + row * (SSTR * 4) + seg * 16,
                      att + (size_t)(q0 + row) * LK + kb + seg * 4);
        }
#pragma unroll
        for (int i = 0; i < 2; i++) {
            int idx = i * 512 + tid;
            int row = idx >> 3, seg = idx & 7;
            cpasync16(vbb + st * VBUF + row * (STRP * 2) + seg * 16,
                      g_vth + (size_t)row * LK + kb + seg * 8);
        }
        CP_COMMIT();
    }

    float o[8][4];
#pragma unroll
    for (int nj = 0; nj < 8; nj++)
#pragma unroll
        for (int e = 0; e < 4; e++) o[nj][e] = 0.f;

    for (int t = 0; t < 16; t++) {
        CP_WAIT(1);
        __syncthreads();

        if (t < 14) {
            const int slot = (t + 2) % 3;
            const int kbn = kbase + (t + 2) * 64;
#pragma unroll
            for (int i = 0; i < 4; i++) {
                int idx = i * 512 + tid;
                int row = idx >> 4, seg = idx & 15;
                cpasync16(sb + slot * SBUF + row * (SSTR * 4) + seg * 16,
                          att + (size_t)(q0 + row) * LK + kbn + seg * 4);
            }
#pragma unroll
            for (int i = 0; i < 2; i++) {
                int idx = i * 512 + tid;
                int row = idx >> 3, seg = idx & 7;
                cpasync16(vbb + slot * VBUF + row * (STRP * 2) + seg * 16,
                          g_vth + (size_t)row * LK + kbn + seg * 8);
            }
        }
        CP_COMMIT();

        const int kb = kbase + t * 64;
        const float* Sc = Ss + (t % 3) * 128 * SSTR;
        const uint32_t vcur = vbb + (t % 3) * VBUF;

        // a) normalized att write-back: disjoint tid-partition, float4 stores
#pragma unroll
        for (int i = 0; i < 4; i++) {
            int idx = i * 512 + tid;
            int row = idx >> 4, col4 = (idx & 15) * 4;
            float4 s = *(const float4*)(Sc + row * SSTR + col4);
            const float il = ilrow[row];
            s.x *= il; s.y *= il; s.z *= il; s.w *= il;
            *(float4*)(att + (size_t)(q0 + row) * LK + kb + col4) = s;
        }

        // b) MMA: A-frags = raw e from S smem (cvt only), B from V smem
#pragma unroll
        for (int k16 = 0; k16 < 4; k16++) {
            const int kc = k16 * 16 + c0;
            const float* rp0 = Sc + (qg + r0) * SSTR + kc;
            const float* rp1 = Sc + (qg + r0 + 8) * SSTR + kc;
            float2 s00 = *(const float2*)rp0;
            float2 s10 = *(const float2*)rp1;
            float2 s01 = *(const float2*)(rp0 + 8);
            float2 s11 = *(const float2*)(rp1 + 8);
            uint32_t ah[4];
            ah[0] = h2u(__floats2half2_rn(s00.x, s00.y));
            ah[1] = h2u(__floats2half2_rn(s10.x, s10.y));
            ah[2] = h2u(__floats2half2_rn(s01.x, s01.y));
            ah[3] = h2u(__floats2half2_rn(s11.x, s11.y));

#pragma unroll
            for (int nj = 0; nj < 4; nj++) {
                uint32_t bv[4];
                ldsm4(bv, vcur + ((dh + nj * 16 + arow) * STRP + k16 * 16 + acol) * 2);
                mma16816(o[2 * nj], ah, bv[0], bv[2]);
                mma16816(o[2 * nj + 1], ah, bv[1], bv[3]);
            }
        }
    }

    float* op = g_opart + (size_t)kcnk * ((size_t)LQ * DIM);
#pragma unroll
    for (int n8 = 0; n8 < 8; n8++) {
        size_t row = (size_t)(q0 + qg + r0);
        size_t col = (size_t)(dh + n8 * 8 + c0);
        *(float2*)(op + row * DIM + col) = make_float2(o[n8][0], o[n8][1]);
        *(float2*)(op + (row + 8) * DIM + col) = make_float2(o[n8][2], o[n8][3]);
    }
}

// ---------------------------------------------------------------------------
// Kernel D: reduce KCH partials into out, applying il[row] once.
// ---------------------------------------------------------------------------
__global__ __launch_bounds__(256) void reduce_kernel(float* __restrict__ out) {
    const size_t i = (size_t)blockIdx.x * 256 + threadIdx.x;
    float s = 0.f;
#pragma unroll
    for (int c = 0; c < KCH; c++) s += g_opart[(size_t)c * LQ * DIM + i];
    out[i] = s * g_il[i >> 7];
}

// ---------------------------------------------------------------------------
extern "C" void kernel_launch(void* const* d_in, const int* in_sizes, int n_in,
                              void* d_out, int out_size) {
    const float* Q = (const float*)d_in[0];
    const float* K = (const float*)d_in[1];
    const float* V = (const float*)d_in[2];
    float* out = (float*)d_out;             // [LQ, DIM]
    float* att = out + (size_t)LQ * DIM;    // [LQ, LK]

    const int smemA = (64 * STRQ + 128 * STRQ) * 2;                  // 52224
    const int smemC = 3 * 128 * SSTR * 4 + 3 * 128 * STRP * 2 + 512; // 166400
    cudaFuncSetAttribute(qk_hmma_kernel, cudaFuncAttributeMaxDynamicSharedMemorySize, smemA);
    cudaFuncSetAttribute(pv_hmma_kernel, cudaFuncAttributeMaxDynamicSharedMemorySize, smemC);

    prep_kernel<<<(LQ * DIM) / 256, 256>>>(Q, K, V);
    qk_hmma_kernel<<<dim3(LK / 128, LQ / 64), 256, smemA>>>(att);
    lred_kernel<<<LQ / 256, 256>>>();
    pv_hmma_kernel<<<dim3(KCH, LQ / 128), 512, smemC>>>(att);
    reduce_kernel<<<(LQ * DIM) / 256, 256>>>(out);
}